// round 1
// baseline (speedup 1.0000x reference)
#include <cuda_runtime.h>
#include <math.h>
#include <stdint.h>

// Problem constants
#define BB    2
#define NSEQ  2048
#define DMOD  1024
#define HN    16
#define DH    64
#define MROWS (BB*NSEQ)          // 4096
#define SCALE 0.125f             // Dh^-0.5

// ---------------- scratch (device globals: allocation-free) ----------------
__device__ float g_xw_qkv[(size_t)MROWS * 3 * DMOD];   // 4096 x 3072
__device__ float g_xw_hkv[(size_t)MROWS * 2 * DMOD];   // 4096 x 2048
__device__ float g_Q [(size_t)BB*HN*NSEQ*DH];
__device__ float g_K [(size_t)BB*HN*NSEQ*DH];
__device__ float g_V [(size_t)BB*HN*NSEQ*DH];
__device__ float g_HK[(size_t)BB*HN*NSEQ*DH];
__device__ float g_HV[(size_t)BB*HN*NSEQ*DH];
__device__ float g_attn[(size_t)MROWS * DMOD];

// ---------------- generic tiled SGEMM: C = A(MxK) * B(KxN) [+bias] --------
// BM=128, BN=128, BK=8, 256 threads, 8x8 per-thread tile.
template<bool BIAS>
__global__ __launch_bounds__(256) void sgemm_k(
    const float* __restrict__ A, const float* __restrict__ B,
    const float* __restrict__ bias, float* __restrict__ C,
    int M, int Nc, int K)
{
    __shared__ float As[8][128];
    __shared__ float Bs[8][128];
    const int tid = threadIdx.x;
    const int bx = blockIdx.x, by = blockIdx.y;
    const int tx = tid & 15, ty = tid >> 4;

    const float* Ab = A + (size_t)(by * 128) * K;
    const float* Bb = B + (size_t)bx * 128;

    const int aRow = tid >> 1;            // 0..127
    const int aCol = (tid & 1) * 4;       // 0 or 4
    const int bRow = tid >> 5;            // 0..7
    const int bCol = (tid & 31) * 4;      // 0..124

    float acc[8][8];
    #pragma unroll
    for (int i = 0; i < 8; i++)
        #pragma unroll
        for (int j = 0; j < 8; j++) acc[i][j] = 0.f;

    for (int k0 = 0; k0 < K; k0 += 8) {
        float4 av = *(const float4*)(Ab + (size_t)aRow * K + k0 + aCol);
        As[aCol + 0][aRow] = av.x;
        As[aCol + 1][aRow] = av.y;
        As[aCol + 2][aRow] = av.z;
        As[aCol + 3][aRow] = av.w;
        *(float4*)&Bs[bRow][bCol] =
            *(const float4*)(Bb + (size_t)(k0 + bRow) * Nc + bCol);
        __syncthreads();
        #pragma unroll
        for (int kk = 0; kk < 8; kk++) {
            float a[8], b[8];
            *(float4*)(a)     = *(float4*)&As[kk][ty * 8];
            *(float4*)(a + 4) = *(float4*)&As[kk][ty * 8 + 4];
            *(float4*)(b)     = *(float4*)&Bs[kk][tx * 8];
            *(float4*)(b + 4) = *(float4*)&Bs[kk][tx * 8 + 4];
            #pragma unroll
            for (int i = 0; i < 8; i++)
                #pragma unroll
                for (int j = 0; j < 8; j++)
                    acc[i][j] = fmaf(a[i], b[j], acc[i][j]);
        }
        __syncthreads();
    }

    #pragma unroll
    for (int i = 0; i < 8; i++) {
        int row = by * 128 + ty * 8 + i;
        int col0 = bx * 128 + tx * 8;
        float* Cp = C + (size_t)row * Nc + col0;
        #pragma unroll
        for (int jg = 0; jg < 8; jg += 4) {
            float4 o;
            o.x = acc[i][jg + 0];
            o.y = acc[i][jg + 1];
            o.z = acc[i][jg + 2];
            o.w = acc[i][jg + 3];
            if (BIAS) {
                o.x += bias[col0 + jg + 0];
                o.y += bias[col0 + jg + 1];
                o.z += bias[col0 + jg + 2];
                o.w += bias[col0 + jg + 3];
            }
            *(float4*)(Cp + jg) = o;
        }
    }
}

// ---------------- scatter to head layout + RoPE on q,k ---------------------
// one thread per (b,h,n,pair i): handles q/k pairs (roped) + v/hk/hv pairs.
__global__ __launch_bounds__(256) void scatter_rope_k(
    const float* __restrict__ xwq, const float* __restrict__ xwh,
    float* __restrict__ Q, float* __restrict__ K, float* __restrict__ V,
    float* __restrict__ HK, float* __restrict__ HV)
{
    int idx = blockIdx.x * blockDim.x + threadIdx.x;
    const int total = BB * HN * NSEQ * (DH / 2);
    if (idx >= total) return;
    int i = idx & 31;
    int n = (idx >> 5) & (NSEQ - 1);
    int h = (idx >> 16) & (HN - 1);
    int b = idx >> 20;

    size_t row = (size_t)b * NSEQ + n;
    const float* xq = xwq + row * (3 * DMOD);
    const float* xh = xwh + row * (2 * DMOD);
    int col = h * DH + 2 * i;

    float q0 = xq[col],            q1 = xq[col + 1];
    float k0 = xq[DMOD + col],     k1 = xq[DMOD + col + 1];
    float v0 = xq[2 * DMOD + col], v1 = xq[2 * DMOD + col + 1];
    float hk0 = xh[col],           hk1 = xh[col + 1];
    float hv0 = xh[DMOD + col],    hv1 = xh[DMOD + col + 1];

    // RoPE: freq = 10000^(-2i/64); angle in fp64, rounded to fp32 like the ref
    double freq = pow(10000.0, -(double)(2 * i) / 64.0);
    float ang = (float)((double)n * freq);
    float s, c;
    sincosf(ang, &s, &c);
    float qr0 = q0 * c - q1 * s, qr1 = q1 * c + q0 * s;
    float kr0 = k0 * c - k1 * s, kr1 = k1 * c + k0 * s;

    size_t o = (((size_t)(b * HN + h) * NSEQ) + n) * DH + 2 * i;
    Q[o] = qr0;  Q[o + 1] = qr1;
    K[o] = kr0;  K[o + 1] = kr1;
    V[o] = v0;   V[o + 1] = v1;
    HK[o] = hk0; HK[o + 1] = hk1;
    HV[o] = hv0; HV[o + 1] = hv1;
}

// ---------------- fused flash attention with silu-modulated scores ---------
// 64x64 tiles, 256 threads (16x16), 4x4 micro-tile.
#define ALD 68   // 68*4B = 272B = 17*16B -> float4-aligned rows
#define ASMEM (7 * 64 * ALD * 4)

__global__ __launch_bounds__(256) void attn_k(
    const float* __restrict__ Q, const float* __restrict__ K,
    const float* __restrict__ V, const float* __restrict__ HK,
    const float* __restrict__ HV, const float* __restrict__ alpha,
    float* __restrict__ Out)
{
    extern __shared__ float sm[];
    float* sQt  = sm;                 // [64][ALD] d-major (transposed)
    float* sHKt = sQt  + 64 * ALD;
    float* sHVt = sHKt + 64 * ALD;
    float* sKt  = sHVt + 64 * ALD;
    float* sVt  = sKt  + 64 * ALD;
    float* sVr  = sVt  + 64 * ALD;    // [m][ALD] row-major V
    float* sP   = sVr  + 64 * ALD;    // [r][ALD]

    const int tid = threadIdx.x;
    const int tx = tid & 15, ty = tid >> 4;
    const int bh = blockIdx.y;
    const int h = bh & (HN - 1);
    const int b = bh >> 4;
    const int qt = gridDim.x - 1 - blockIdx.x;   // big tiles first
    const size_t base = (size_t)bh * NSEQ * DH;
    const float NEGINF = __int_as_float(0xff800000);

    // load Q/HK/HV tiles transposed
    #pragma unroll
    for (int r = 0; r < 4; r++) {
        int fi = tid + r * 256;
        int m = fi >> 4, dg = (fi & 15) * 4;
        size_t g = base + (size_t)(qt * 64 + m) * DH + dg;
        float4 q = *(const float4*)(Q + g);
        sQt[(dg + 0) * ALD + m] = q.x; sQt[(dg + 1) * ALD + m] = q.y;
        sQt[(dg + 2) * ALD + m] = q.z; sQt[(dg + 3) * ALD + m] = q.w;
        float4 a = *(const float4*)(HK + g);
        sHKt[(dg + 0) * ALD + m] = a.x; sHKt[(dg + 1) * ALD + m] = a.y;
        sHKt[(dg + 2) * ALD + m] = a.z; sHKt[(dg + 3) * ALD + m] = a.w;
        float4 v = *(const float4*)(HV + g);
        sHVt[(dg + 0) * ALD + m] = v.x; sHVt[(dg + 1) * ALD + m] = v.y;
        sHVt[(dg + 2) * ALD + m] = v.z; sHVt[(dg + 3) * ALD + m] = v.w;
    }
    __syncthreads();

    // per-row qhk = sum_d q*hk (reduced across the 16 tx lanes)
    float qhk[4];
    #pragma unroll
    for (int i = 0; i < 4; i++) {
        int rr = ty * 4 + i;
        float s = 0.f;
        #pragma unroll
        for (int dd = 0; dd < 4; dd++) {
            int d = tx * 4 + dd;
            s += sQt[d * ALD + rr] * sHKt[d * ALD + rr];
        }
        s += __shfl_xor_sync(0xffffffffu, s, 8);
        s += __shfl_xor_sync(0xffffffffu, s, 4);
        s += __shfl_xor_sync(0xffffffffu, s, 2);
        s += __shfl_xor_sync(0xffffffffu, s, 1);
        qhk[i] = s;
    }

    float rmax[4], lsum[4], accm[4], acco[4][4];
    #pragma unroll
    for (int i = 0; i < 4; i++) {
        rmax[i] = NEGINF; lsum[i] = 0.f; accm[i] = 0.f;
        #pragma unroll
        for (int j = 0; j < 4; j++) acco[i][j] = 0.f;
    }
    const float sigA = 1.f / (1.f + __expf(-alpha[h]));

    for (int kt = 0; kt <= qt; ++kt) {
        __syncthreads();   // previous p@V done before overwriting K/V tiles
        #pragma unroll
        for (int r = 0; r < 4; r++) {
            int fi = tid + r * 256;
            int m = fi >> 4, dg = (fi & 15) * 4;
            size_t g = base + (size_t)(kt * 64 + m) * DH + dg;
            float4 kv = *(const float4*)(K + g);
            sKt[(dg + 0) * ALD + m] = kv.x; sKt[(dg + 1) * ALD + m] = kv.y;
            sKt[(dg + 2) * ALD + m] = kv.z; sKt[(dg + 3) * ALD + m] = kv.w;
            float4 vv = *(const float4*)(V + g);
            sVt[(dg + 0) * ALD + m] = vv.x; sVt[(dg + 1) * ALD + m] = vv.y;
            sVt[(dg + 2) * ALD + m] = vv.z; sVt[(dg + 3) * ALD + m] = vv.w;
            *(float4*)&sVr[m * ALD + dg] = vv;
        }
        __syncthreads();

        float S1[4][4], S2[4][4], S3[4][4];
        #pragma unroll
        for (int i = 0; i < 4; i++)
            #pragma unroll
            for (int j = 0; j < 4; j++) { S1[i][j] = 0.f; S2[i][j] = 0.f; S3[i][j] = 0.f; }

        #pragma unroll 8
        for (int d = 0; d < 64; d++) {
            float4 aq = *(float4*)&sQt [d * ALD + ty * 4];
            float4 ah = *(float4*)&sHKt[d * ALD + ty * 4];
            float4 av = *(float4*)&sHVt[d * ALD + ty * 4];
            float4 bk = *(float4*)&sKt [d * ALD + tx * 4];
            float4 bv = *(float4*)&sVt [d * ALD + tx * 4];
            float aqa[4] = {aq.x, aq.y, aq.z, aq.w};
            float aha[4] = {ah.x, ah.y, ah.z, ah.w};
            float ava[4] = {av.x, av.y, av.z, av.w};
            float bka[4] = {bk.x, bk.y, bk.z, bk.w};
            float bva[4] = {bv.x, bv.y, bv.z, bv.w};
            #pragma unroll
            for (int i = 0; i < 4; i++)
                #pragma unroll
                for (int j = 0; j < 4; j++) {
                    S1[i][j] = fmaf(aqa[i], bka[j], S1[i][j]);
                    S2[i][j] = fmaf(aha[i], bka[j], S2[i][j]);
                    S3[i][j] = fmaf(ava[i], bva[j], S3[i][j]);
                }
        }

        // combine scores, causal mask, online softmax update
        #pragma unroll
        for (int i = 0; i < 4; i++) {
            int nr = qt * 64 + ty * 4 + i;
            float sv[4];
            float tmax = NEGINF;
            #pragma unroll
            for (int j = 0; j < 4; j++) {
                int mc = kt * 64 + tx * 4 + j;
                float z = S2[i][j] * qhk[i] * SCALE;
                float sil = z / (1.f + __expf(-z));
                float s = S1[i][j] * SCALE - sil;
                if (mc > nr) s = NEGINF;
                sv[j] = s;
                tmax = fmaxf(tmax, s);
            }
            tmax = fmaxf(tmax, __shfl_xor_sync(0xffffffffu, tmax, 8));
            tmax = fmaxf(tmax, __shfl_xor_sync(0xffffffffu, tmax, 4));
            tmax = fmaxf(tmax, __shfl_xor_sync(0xffffffffu, tmax, 2));
            tmax = fmaxf(tmax, __shfl_xor_sync(0xffffffffu, tmax, 1));
            float nm = fmaxf(rmax[i], tmax);
            float sc = __expf(rmax[i] - nm);
            rmax[i] = nm;
            lsum[i] *= sc; accm[i] *= sc;
            #pragma unroll
            for (int j = 0; j < 4; j++) acco[i][j] *= sc;
            #pragma unroll
            for (int j = 0; j < 4; j++) {
                float p = __expf(sv[j] - nm);
                sP[(ty * 4 + i) * ALD + tx * 4 + j] = p;
                lsum[i] += p;
                accm[i] = fmaf(p, S3[i][j], accm[i]);
            }
        }
        __syncthreads();

        // acc_o += P @ V
        #pragma unroll 4
        for (int kk = 0; kk < 64; kk++) {
            float4 bv = *(float4*)&sVr[kk * ALD + tx * 4];
            #pragma unroll
            for (int i = 0; i < 4; i++) {
                float p = sP[(ty * 4 + i) * ALD + kk];
                acco[i][0] = fmaf(p, bv.x, acco[i][0]);
                acco[i][1] = fmaf(p, bv.y, acco[i][1]);
                acco[i][2] = fmaf(p, bv.z, acco[i][2]);
                acco[i][3] = fmaf(p, bv.w, acco[i][3]);
            }
        }
    }

    // reduce l and mod across the 16 tx lanes
    #pragma unroll
    for (int i = 0; i < 4; i++) {
        float l = lsum[i], m = accm[i];
        l += __shfl_xor_sync(0xffffffffu, l, 8);
        l += __shfl_xor_sync(0xffffffffu, l, 4);
        l += __shfl_xor_sync(0xffffffffu, l, 2);
        l += __shfl_xor_sync(0xffffffffu, l, 1);
        m += __shfl_xor_sync(0xffffffffu, m, 8);
        m += __shfl_xor_sync(0xffffffffu, m, 4);
        m += __shfl_xor_sync(0xffffffffu, m, 2);
        m += __shfl_xor_sync(0xffffffffu, m, 1);
        lsum[i] = l; accm[i] = m;
    }

    // epilogue: o = acc_o/l - sigmoid(alpha)*(mod/l)*hv
    #pragma unroll
    for (int i = 0; i < 4; i++) {
        int rr = ty * 4 + i;
        int nr = qt * 64 + rr;
        float inv = 1.f / lsum[i];
        float mo = accm[i] * inv * sigA;
        float4 o;
        o.x = acco[i][0] * inv - mo * sHVt[(tx * 4 + 0) * ALD + rr];
        o.y = acco[i][1] * inv - mo * sHVt[(tx * 4 + 1) * ALD + rr];
        o.z = acco[i][2] * inv - mo * sHVt[(tx * 4 + 2) * ALD + rr];
        o.w = acco[i][3] * inv - mo * sHVt[(tx * 4 + 3) * ALD + rr];
        size_t go = ((size_t)(b * NSEQ + nr)) * DMOD + h * DH + tx * 4;
        *(float4*)(Out + go) = o;
    }
}

// ---------------- launcher --------------------------------------------------
extern "C" void kernel_launch(void* const* d_in, const int* in_sizes, int n_in,
                              void* d_out, int out_size)
{
    const float* x     = (const float*)d_in[0];
    const float* w_qkv = (const float*)d_in[1];
    const float* w_hkv = (const float*)d_in[2];
    const float* w_out = (const float*)d_in[3];
    const float* b_out = (const float*)d_in[4];
    const float* alpha = (const float*)d_in[5];
    float* out = (float*)d_out;

    float *xwq, *xwh, *Q, *K, *V, *HK, *HV, *attn;
    cudaGetSymbolAddress((void**)&xwq,  g_xw_qkv);
    cudaGetSymbolAddress((void**)&xwh,  g_xw_hkv);
    cudaGetSymbolAddress((void**)&Q,    g_Q);
    cudaGetSymbolAddress((void**)&K,    g_K);
    cudaGetSymbolAddress((void**)&V,    g_V);
    cudaGetSymbolAddress((void**)&HK,   g_HK);
    cudaGetSymbolAddress((void**)&HV,   g_HV);
    cudaGetSymbolAddress((void**)&attn, g_attn);

    cudaFuncSetAttribute(attn_k, cudaFuncAttributeMaxDynamicSharedMemorySize, ASMEM);

    // 1) projections
    sgemm_k<false><<<dim3(3 * DMOD / 128, MROWS / 128), 256>>>(
        x, w_qkv, nullptr, xwq, MROWS, 3 * DMOD, DMOD);
    sgemm_k<false><<<dim3(2 * DMOD / 128, MROWS / 128), 256>>>(
        x, w_hkv, nullptr, xwh, MROWS, 2 * DMOD, DMOD);

    // 2) head scatter + RoPE
    {
        int total = BB * HN * NSEQ * (DH / 2);
        scatter_rope_k<<<(total + 255) / 256, 256>>>(xwq, xwh, Q, K, V, HK, HV);
    }

    // 3) fused attention
    attn_k<<<dim3(NSEQ / 64, BB * HN), 256, ASMEM>>>(Q, K, V, HK, HV, alpha, attn);

    // 4) output projection + bias
    sgemm_k<true><<<dim3(DMOD / 128, MROWS / 128), 256>>>(
        attn, w_out, b_out, out, MROWS, DMOD, DMOD);
}

// round 4
// speedup vs baseline: 1.3536x; 1.3536x over previous
#include <cuda_runtime.h>
#include <cuda_bf16.h>
#include <math.h>
#include <stdint.h>

// Problem constants
#define BB    2
#define NSEQ  2048
#define DMOD  1024
#define HN    16
#define DH    64
#define MROWS (BB*NSEQ)          // 4096
#define SCALE 0.125f             // Dh^-0.5

// ---------------- scratch (device globals: allocation-free) ----------------
__device__ __align__(256) float g_xw_qkv[(size_t)MROWS * 3 * DMOD];   // 4096 x 3072
__device__ __align__(256) float g_xw_hkv[(size_t)MROWS * 2 * DMOD];   // 4096 x 2048
__device__ __align__(256) float g_Q [(size_t)BB*HN*NSEQ*DH];
__device__ __align__(256) float g_K [(size_t)BB*HN*NSEQ*DH];
__device__ __align__(256) float g_V [(size_t)BB*HN*NSEQ*DH];
__device__ __align__(256) float g_HK[(size_t)BB*HN*NSEQ*DH];
__device__ __align__(256) float g_HV[(size_t)BB*HN*NSEQ*DH];
__device__ __align__(256) float g_attn[(size_t)MROWS * DMOD];

// packed bf16 operands: A row-major [M,K], B^T row-major [N,K]; hi/lo split
__device__ __align__(256) __nv_bfloat16 g_Axh[(size_t)MROWS * DMOD];
__device__ __align__(256) __nv_bfloat16 g_Axl[(size_t)MROWS * DMOD];
__device__ __align__(256) __nv_bfloat16 g_Ath[(size_t)MROWS * DMOD];
__device__ __align__(256) __nv_bfloat16 g_Atl[(size_t)MROWS * DMOD];
__device__ __align__(256) __nv_bfloat16 g_Bqh[(size_t)3 * DMOD * DMOD];
__device__ __align__(256) __nv_bfloat16 g_Bql[(size_t)3 * DMOD * DMOD];
__device__ __align__(256) __nv_bfloat16 g_Bhh[(size_t)2 * DMOD * DMOD];
__device__ __align__(256) __nv_bfloat16 g_Bhl[(size_t)2 * DMOD * DMOD];
__device__ __align__(256) __nv_bfloat16 g_Boh[(size_t)DMOD * DMOD];
__device__ __align__(256) __nv_bfloat16 g_Bol[(size_t)DMOD * DMOD];

// ======================= PTX helpers (compute_103-safe) ====================
__device__ __forceinline__ uint32_t smem_u32(const void* p) {
    uint32_t a;
    asm("{ .reg .u64 t; cvta.to.shared.u64 t, %1; cvt.u32.u64 %0, t; }" : "=r"(a) : "l"(p));
    return a;
}
__device__ __forceinline__ void cpasync16(uint32_t dst, const void* src) {
    asm volatile("cp.async.cg.shared.global [%0], [%1], 16;" :: "r"(dst), "l"(src));
}
__device__ __forceinline__ void cp_commit() {
    asm volatile("cp.async.commit_group;");
}
template<int N>
__device__ __forceinline__ void cp_wait() {
    asm volatile("cp.async.wait_group %0;" :: "n"(N));
}
__device__ __forceinline__ void ldsm4(uint32_t& r0, uint32_t& r1, uint32_t& r2, uint32_t& r3,
                                      uint32_t addr) {
    asm volatile("ldmatrix.sync.aligned.m8n8.x4.shared.b16 {%0,%1,%2,%3}, [%4];"
        : "=r"(r0), "=r"(r1), "=r"(r2), "=r"(r3) : "r"(addr));
}
__device__ __forceinline__ void mma_bf16(float* d, const uint32_t* a,
                                         uint32_t b0, uint32_t b1) {
    asm volatile("mma.sync.aligned.m16n8k16.row.col.f32.bf16.bf16.f32 "
        "{%0,%1,%2,%3}, {%4,%5,%6,%7}, {%8,%9}, {%0,%1,%2,%3};"
        : "+f"(d[0]), "+f"(d[1]), "+f"(d[2]), "+f"(d[3])
        : "r"(a[0]), "r"(a[1]), "r"(a[2]), "r"(a[3]), "r"(b0), "r"(b1));
}

// ======================= pack kernels ======================================
// A [M,K] fp32 -> bf16 hi/lo, same layout (vectorized)
__global__ __launch_bounds__(256) void packA_k(
    const float* __restrict__ A, __nv_bfloat16* __restrict__ hi,
    __nv_bfloat16* __restrict__ lo, int n4)   // n4 = total/4
{
    int idx = blockIdx.x * blockDim.x + threadIdx.x;
    if (idx >= n4) return;
    float4 v = ((const float4*)A)[idx];
    __nv_bfloat16 h[4], l[4];
    float vv[4] = {v.x, v.y, v.z, v.w};
    #pragma unroll
    for (int i = 0; i < 4; i++) {
        h[i] = __float2bfloat16(vv[i]);
        l[i] = __float2bfloat16(vv[i] - __bfloat162float(h[i]));
    }
    ((uint2*)hi)[idx] = *(uint2*)h;
    ((uint2*)lo)[idx] = *(uint2*)l;
}

// W [K,N] fp32 -> B^T [N,K] bf16 hi/lo (smem transpose)
__global__ __launch_bounds__(256) void packB_k(
    const float* __restrict__ W, __nv_bfloat16* __restrict__ hi,
    __nv_bfloat16* __restrict__ lo, int K, int N)
{
    __shared__ float s[32][33];
    int n0 = blockIdx.x * 32, k0 = blockIdx.y * 32;
    int tx = threadIdx.x & 31, ty = threadIdx.x >> 5;   // 32 x 8
    #pragma unroll
    for (int i = 0; i < 4; i++) {
        int k = ty + i * 8;
        s[k][tx] = W[(size_t)(k0 + k) * N + n0 + tx];
    }
    __syncthreads();
    #pragma unroll
    for (int i = 0; i < 4; i++) {
        int nl = ty + i * 8;
        float v = s[tx][nl];
        __nv_bfloat16 h = __float2bfloat16(v);
        __nv_bfloat16 l = __float2bfloat16(v - __bfloat162float(h));
        size_t o = (size_t)(n0 + nl) * K + k0 + tx;
        hi[o] = h;
        lo[o] = l;
    }
}

// ======================= mma.sync bf16 GEMM ================================
// C[M,N] = sum_k A[m,k] * Bt[n,k], hi/lo split (3 passes), fp32 accum.
// CTA: 128x128, BK=32, 256 threads = 8 warps (2 x 4), warp tile 64x32.
#define GLDB   80                      // smem row stride in bytes (32 bf16 + 8 pad)
#define MATB   (128 * GLDB)            // 10240 B per matrix per stage
#define STAGEB (4 * MATB)              // Ah, Al, Bh, Bl
#define GSMEM  (2 * STAGEB)            // 81920 B

__global__ __launch_bounds__(256) void gemm_tc(
    const __nv_bfloat16* __restrict__ Ahi, const __nv_bfloat16* __restrict__ Alo,
    const __nv_bfloat16* __restrict__ Bhi, const __nv_bfloat16* __restrict__ Blo,
    const float* __restrict__ bias, float* __restrict__ C,
    int N, int K, int hasBias)
{
    extern __shared__ char smraw[];
    const uint32_t sb = smem_u32(smraw);
    const int tid = threadIdx.x;
    const int lane = tid & 31, wid = tid >> 5;
    const int wm = wid >> 2;          // 0..1 (64-row half)
    const int wn = wid & 3;           // 0..3 (32-col quarter)

    const int bm = blockIdx.y * 128;
    const int bn = blockIdx.x * 128;

    const __nv_bfloat16* srcs[4] = {
        Ahi + (size_t)bm * K, Alo + (size_t)bm * K,
        Bhi + (size_t)bn * K, Blo + (size_t)bn * K };

    // loader: 2048 x 16B chunks per stage, 8 per thread
    const int lrem = tid;        // base index
    auto load_stage = [&](int st, int kc) {
        #pragma unroll
        for (int i = 0; i < 8; i++) {
            int idx = lrem + i * 256;
            int mat = idx >> 9;
            int rem = idx & 511;
            int r = rem >> 2, ch = rem & 3;
            const __nv_bfloat16* g = srcs[mat] + (size_t)r * K + kc * 32 + ch * 8;
            cpasync16(sb + st * STAGEB + mat * MATB + r * GLDB + ch * 16, g);
        }
        cp_commit();
    };

    float acc[4][4][4];
    #pragma unroll
    for (int a = 0; a < 4; a++)
        #pragma unroll
        for (int b = 0; b < 4; b++)
            #pragma unroll
            for (int c = 0; c < 4; c++) acc[a][b][c] = 0.f;

    const int KC = K >> 5;   // k chunks of 32
    load_stage(0, 0);

    const int arow = lane & 15;
    const int ahalf = (lane >> 4) << 3;    // 0 or 8 (bf16 col offset)

    for (int kc = 0; kc < KC; kc++) {
        int cur = kc & 1;
        if (kc + 1 < KC) load_stage(1 - cur, kc + 1);
        if (kc + 1 < KC) cp_wait<1>(); else cp_wait<0>();
        __syncthreads();

        #pragma unroll
        for (int kk = 0; kk < 32; kk += 16) {
            uint32_t ah[4][4], al[4][4], bh[2][4], bl[2][4];
            int acol = kk + ahalf;
            uint32_t stbase = sb + cur * STAGEB;
            #pragma unroll
            for (int mb = 0; mb < 4; mb++) {
                int r = wm * 64 + mb * 16 + arow;
                uint32_t ad = stbase + r * GLDB + acol * 2;
                ldsm4(ah[mb][0], ah[mb][1], ah[mb][2], ah[mb][3], ad);
                ldsm4(al[mb][0], al[mb][1], al[mb][2], al[mb][3], ad + MATB);
            }
            #pragma unroll
            for (int p = 0; p < 2; p++) {
                int r = wn * 32 + p * 16 + arow;
                uint32_t bd = stbase + 2 * MATB + r * GLDB + acol * 2;
                ldsm4(bh[p][0], bh[p][1], bh[p][2], bh[p][3], bd);
                ldsm4(bl[p][0], bl[p][1], bl[p][2], bl[p][3], bd + MATB);
            }
            #pragma unroll
            for (int mb = 0; mb < 4; mb++)
                #pragma unroll
                for (int nb = 0; nb < 4; nb++) {
                    int p = nb >> 1, hf = nb & 1;
                    mma_bf16(acc[mb][nb], ah[mb], bh[p][hf], bh[p][hf + 2]);
                    mma_bf16(acc[mb][nb], ah[mb], bl[p][hf], bl[p][hf + 2]);
                    mma_bf16(acc[mb][nb], al[mb], bh[p][hf], bh[p][hf + 2]);
                }
        }
        __syncthreads();
    }

    // epilogue: lane t holds C[m + t/4 (+8)][n + (t%4)*2 + {0,1}]
    #pragma unroll
    for (int mb = 0; mb < 4; mb++) {
        int r0 = bm + wm * 64 + mb * 16 + (lane >> 2);
        #pragma unroll
        for (int nb = 0; nb < 4; nb++) {
            int c0 = bn + wn * 32 + nb * 8 + (lane & 3) * 2;
            float bx = 0.f, by = 0.f;
            if (hasBias) { bx = bias[c0]; by = bias[c0 + 1]; }
            float2 v0 = { acc[mb][nb][0] + bx, acc[mb][nb][1] + by };
            float2 v1 = { acc[mb][nb][2] + bx, acc[mb][nb][3] + by };
            *(float2*)(C + (size_t)r0 * N + c0) = v0;
            *(float2*)(C + (size_t)(r0 + 8) * N + c0) = v1;
        }
    }
}

// ---------------- scatter to head layout + RoPE on q,k ---------------------
__global__ __launch_bounds__(256) void scatter_rope_k(
    const float* __restrict__ xwq, const float* __restrict__ xwh,
    float* __restrict__ Q, float* __restrict__ K, float* __restrict__ V,
    float* __restrict__ HK, float* __restrict__ HV)
{
    int idx = blockIdx.x * blockDim.x + threadIdx.x;
    const int total = BB * HN * NSEQ * (DH / 2);
    if (idx >= total) return;
    int i = idx & 31;
    int n = (idx >> 5) & (NSEQ - 1);
    int h = (idx >> 16) & (HN - 1);
    int b = idx >> 20;

    size_t row = (size_t)b * NSEQ + n;
    const float* xq = xwq + row * (3 * DMOD);
    const float* xh = xwh + row * (2 * DMOD);
    int col = h * DH + 2 * i;

    float q0 = xq[col],            q1 = xq[col + 1];
    float k0 = xq[DMOD + col],     k1 = xq[DMOD + col + 1];
    float v0 = xq[2 * DMOD + col], v1 = xq[2 * DMOD + col + 1];
    float hk0 = xh[col],           hk1 = xh[col + 1];
    float hv0 = xh[DMOD + col],    hv1 = xh[DMOD + col + 1];

    double freq = pow(10000.0, -(double)(2 * i) / 64.0);
    float ang = (float)((double)n * freq);
    float s, c;
    sincosf(ang, &s, &c);
    float qr0 = q0 * c - q1 * s, qr1 = q1 * c + q0 * s;
    float kr0 = k0 * c - k1 * s, kr1 = k1 * c + k0 * s;

    size_t o = (((size_t)(b * HN + h) * NSEQ) + n) * DH + 2 * i;
    Q[o] = qr0;  Q[o + 1] = qr1;
    K[o] = kr0;  K[o + 1] = kr1;
    V[o] = v0;   V[o + 1] = v1;
    HK[o] = hk0; HK[o + 1] = hk1;
    HV[o] = hv0; HV[o + 1] = hv1;
}

// ---------------- fused flash attention with silu-modulated scores ---------
#define ALD 68
#define ASMEM (7 * 64 * ALD * 4)

__global__ __launch_bounds__(256) void attn_k(
    const float* __restrict__ Q, const float* __restrict__ K,
    const float* __restrict__ V, const float* __restrict__ HK,
    const float* __restrict__ HV, const float* __restrict__ alpha,
    float* __restrict__ Out)
{
    extern __shared__ float sm[];
    float* sQt  = sm;
    float* sHKt = sQt  + 64 * ALD;
    float* sHVt = sHKt + 64 * ALD;
    float* sKt  = sHVt + 64 * ALD;
    float* sVt  = sKt  + 64 * ALD;
    float* sVr  = sVt  + 64 * ALD;
    float* sP   = sVr  + 64 * ALD;

    const int tid = threadIdx.x;
    const int tx = tid & 15, ty = tid >> 4;
    const int bh = blockIdx.y;
    const int h = bh & (HN - 1);
    const int b = bh >> 4;
    const int qt = gridDim.x - 1 - blockIdx.x;
    const size_t base = (size_t)bh * NSEQ * DH;
    const float NEGINF = __int_as_float(0xff800000);

    #pragma unroll
    for (int r = 0; r < 4; r++) {
        int fi = tid + r * 256;
        int m = fi >> 4, dg = (fi & 15) * 4;
        size_t g = base + (size_t)(qt * 64 + m) * DH + dg;
        float4 q = *(const float4*)(Q + g);
        sQt[(dg + 0) * ALD + m] = q.x; sQt[(dg + 1) * ALD + m] = q.y;
        sQt[(dg + 2) * ALD + m] = q.z; sQt[(dg + 3) * ALD + m] = q.w;
        float4 a = *(const float4*)(HK + g);
        sHKt[(dg + 0) * ALD + m] = a.x; sHKt[(dg + 1) * ALD + m] = a.y;
        sHKt[(dg + 2) * ALD + m] = a.z; sHKt[(dg + 3) * ALD + m] = a.w;
        float4 v = *(const float4*)(HV + g);
        sHVt[(dg + 0) * ALD + m] = v.x; sHVt[(dg + 1) * ALD + m] = v.y;
        sHVt[(dg + 2) * ALD + m] = v.z; sHVt[(dg + 3) * ALD + m] = v.w;
    }
    __syncthreads();

    float qhk[4];
    #pragma unroll
    for (int i = 0; i < 4; i++) {
        int rr = ty * 4 + i;
        float s = 0.f;
        #pragma unroll
        for (int dd = 0; dd < 4; dd++) {
            int d = tx * 4 + dd;
            s += sQt[d * ALD + rr] * sHKt[d * ALD + rr];
        }
        s += __shfl_xor_sync(0xffffffffu, s, 8);
        s += __shfl_xor_sync(0xffffffffu, s, 4);
        s += __shfl_xor_sync(0xffffffffu, s, 2);
        s += __shfl_xor_sync(0xffffffffu, s, 1);
        qhk[i] = s;
    }

    float rmax[4], lsum[4], accm[4], acco[4][4];
    #pragma unroll
    for (int i = 0; i < 4; i++) {
        rmax[i] = NEGINF; lsum[i] = 0.f; accm[i] = 0.f;
        #pragma unroll
        for (int j = 0; j < 4; j++) acco[i][j] = 0.f;
    }
    const float sigA = 1.f / (1.f + __expf(-alpha[h]));

    for (int kt = 0; kt <= qt; ++kt) {
        __syncthreads();
        #pragma unroll
        for (int r = 0; r < 4; r++) {
            int fi = tid + r * 256;
            int m = fi >> 4, dg = (fi & 15) * 4;
            size_t g = base + (size_t)(kt * 64 + m) * DH + dg;
            float4 kv = *(const float4*)(K + g);
            sKt[(dg + 0) * ALD + m] = kv.x; sKt[(dg + 1) * ALD + m] = kv.y;
            sKt[(dg + 2) * ALD + m] = kv.z; sKt[(dg + 3) * ALD + m] = kv.w;
            float4 vv = *(const float4*)(V + g);
            sVt[(dg + 0) * ALD + m] = vv.x; sVt[(dg + 1) * ALD + m] = vv.y;
            sVt[(dg + 2) * ALD + m] = vv.z; sVt[(dg + 3) * ALD + m] = vv.w;
            *(float4*)&sVr[m * ALD + dg] = vv;
        }
        __syncthreads();

        float S1[4][4], S2[4][4], S3[4][4];
        #pragma unroll
        for (int i = 0; i < 4; i++)
            #pragma unroll
            for (int j = 0; j < 4; j++) { S1[i][j] = 0.f; S2[i][j] = 0.f; S3[i][j] = 0.f; }

        #pragma unroll 8
        for (int d = 0; d < 64; d++) {
            float4 aq = *(float4*)&sQt [d * ALD + ty * 4];
            float4 ah = *(float4*)&sHKt[d * ALD + ty * 4];
            float4 av = *(float4*)&sHVt[d * ALD + ty * 4];
            float4 bk = *(float4*)&sKt [d * ALD + tx * 4];
            float4 bv = *(float4*)&sVt [d * ALD + tx * 4];
            float aqa[4] = {aq.x, aq.y, aq.z, aq.w};
            float aha[4] = {ah.x, ah.y, ah.z, ah.w};
            float ava[4] = {av.x, av.y, av.z, av.w};
            float bka[4] = {bk.x, bk.y, bk.z, bk.w};
            float bva[4] = {bv.x, bv.y, bv.z, bv.w};
            #pragma unroll
            for (int i = 0; i < 4; i++)
                #pragma unroll
                for (int j = 0; j < 4; j++) {
                    S1[i][j] = fmaf(aqa[i], bka[j], S1[i][j]);
                    S2[i][j] = fmaf(aha[i], bka[j], S2[i][j]);
                    S3[i][j] = fmaf(ava[i], bva[j], S3[i][j]);
                }
        }

        #pragma unroll
        for (int i = 0; i < 4; i++) {
            int nr = qt * 64 + ty * 4 + i;
            float sv[4];
            float tmax = NEGINF;
            #pragma unroll
            for (int j = 0; j < 4; j++) {
                int mc = kt * 64 + tx * 4 + j;
                float z = S2[i][j] * qhk[i] * SCALE;
                float sil = z / (1.f + __expf(-z));
                float s = S1[i][j] * SCALE - sil;
                if (mc > nr) s = NEGINF;
                sv[j] = s;
                tmax = fmaxf(tmax, s);
            }
            tmax = fmaxf(tmax, __shfl_xor_sync(0xffffffffu, tmax, 8));
            tmax = fmaxf(tmax, __shfl_xor_sync(0xffffffffu, tmax, 4));
            tmax = fmaxf(tmax, __shfl_xor_sync(0xffffffffu, tmax, 2));
            tmax = fmaxf(tmax, __shfl_xor_sync(0xffffffffu, tmax, 1));
            float nm = fmaxf(rmax[i], tmax);
            float sc = __expf(rmax[i] - nm);
            rmax[i] = nm;
            lsum[i] *= sc; accm[i] *= sc;
            #pragma unroll
            for (int j = 0; j < 4; j++) acco[i][j] *= sc;
            #pragma unroll
            for (int j = 0; j < 4; j++) {
                float p = __expf(sv[j] - nm);
                sP[(ty * 4 + i) * ALD + tx * 4 + j] = p;
                lsum[i] += p;
                accm[i] = fmaf(p, S3[i][j], accm[i]);
            }
        }
        __syncthreads();

        #pragma unroll 4
        for (int kk = 0; kk < 64; kk++) {
            float4 bv = *(float4*)&sVr[kk * ALD + tx * 4];
            #pragma unroll
            for (int i = 0; i < 4; i++) {
                float p = sP[(ty * 4 + i) * ALD + kk];
                acco[i][0] = fmaf(p, bv.x, acco[i][0]);
                acco[i][1] = fmaf(p, bv.y, acco[i][1]);
                acco[i][2] = fmaf(p, bv.z, acco[i][2]);
                acco[i][3] = fmaf(p, bv.w, acco[i][3]);
            }
        }
    }

    #pragma unroll
    for (int i = 0; i < 4; i++) {
        float l = lsum[i], m = accm[i];
        l += __shfl_xor_sync(0xffffffffu, l, 8);
        l += __shfl_xor_sync(0xffffffffu, l, 4);
        l += __shfl_xor_sync(0xffffffffu, l, 2);
        l += __shfl_xor_sync(0xffffffffu, l, 1);
        m += __shfl_xor_sync(0xffffffffu, m, 8);
        m += __shfl_xor_sync(0xffffffffu, m, 4);
        m += __shfl_xor_sync(0xffffffffu, m, 2);
        m += __shfl_xor_sync(0xffffffffu, m, 1);
        lsum[i] = l; accm[i] = m;
    }

    #pragma unroll
    for (int i = 0; i < 4; i++) {
        int rr = ty * 4 + i;
        int nr = qt * 64 + rr;
        float inv = 1.f / lsum[i];
        float mo = accm[i] * inv * sigA;
        float4 o;
        o.x = acco[i][0] * inv - mo * sHVt[(tx * 4 + 0) * ALD + rr];
        o.y = acco[i][1] * inv - mo * sHVt[(tx * 4 + 1) * ALD + rr];
        o.z = acco[i][2] * inv - mo * sHVt[(tx * 4 + 2) * ALD + rr];
        o.w = acco[i][3] * inv - mo * sHVt[(tx * 4 + 3) * ALD + rr];
        size_t go = ((size_t)(b * NSEQ + nr)) * DMOD + h * DH + tx * 4;
        *(float4*)(Out + go) = o;
    }
}

// ---------------- launcher --------------------------------------------------
extern "C" void kernel_launch(void* const* d_in, const int* in_sizes, int n_in,
                              void* d_out, int out_size)
{
    const float* x     = (const float*)d_in[0];
    const float* w_qkv = (const float*)d_in[1];
    const float* w_hkv = (const float*)d_in[2];
    const float* w_out = (const float*)d_in[3];
    const float* b_out = (const float*)d_in[4];
    const float* alpha = (const float*)d_in[5];
    float* out = (float*)d_out;

    float *xwq, *xwh, *Q, *K, *V, *HK, *HV, *attn;
    __nv_bfloat16 *Axh, *Axl, *Ath, *Atl, *Bqh, *Bql, *Bhh, *Bhl, *Boh, *Bol;
    cudaGetSymbolAddress((void**)&xwq,  g_xw_qkv);
    cudaGetSymbolAddress((void**)&xwh,  g_xw_hkv);
    cudaGetSymbolAddress((void**)&Q,    g_Q);
    cudaGetSymbolAddress((void**)&K,    g_K);
    cudaGetSymbolAddress((void**)&V,    g_V);
    cudaGetSymbolAddress((void**)&HK,   g_HK);
    cudaGetSymbolAddress((void**)&HV,   g_HV);
    cudaGetSymbolAddress((void**)&attn, g_attn);
    cudaGetSymbolAddress((void**)&Axh,  g_Axh);
    cudaGetSymbolAddress((void**)&Axl,  g_Axl);
    cudaGetSymbolAddress((void**)&Ath,  g_Ath);
    cudaGetSymbolAddress((void**)&Atl,  g_Atl);
    cudaGetSymbolAddress((void**)&Bqh,  g_Bqh);
    cudaGetSymbolAddress((void**)&Bql,  g_Bql);
    cudaGetSymbolAddress((void**)&Bhh,  g_Bhh);
    cudaGetSymbolAddress((void**)&Bhl,  g_Bhl);
    cudaGetSymbolAddress((void**)&Boh,  g_Boh);
    cudaGetSymbolAddress((void**)&Bol,  g_Bol);

    cudaFuncSetAttribute(attn_k, cudaFuncAttributeMaxDynamicSharedMemorySize, ASMEM);
    cudaFuncSetAttribute(gemm_tc, cudaFuncAttributeMaxDynamicSharedMemorySize, GSMEM);

    // 0) pack operands to bf16 hi/lo
    packA_k<<<(MROWS * DMOD / 4 + 255) / 256, 256>>>(x, Axh, Axl, MROWS * DMOD / 4);
    packB_k<<<dim3(3 * DMOD / 32, DMOD / 32), 256>>>(w_qkv, Bqh, Bql, DMOD, 3 * DMOD);
    packB_k<<<dim3(2 * DMOD / 32, DMOD / 32), 256>>>(w_hkv, Bhh, Bhl, DMOD, 2 * DMOD);
    packB_k<<<dim3(DMOD / 32, DMOD / 32), 256>>>(w_out, Boh, Bol, DMOD, DMOD);

    // 1) projections on tensor cores (mma.sync bf16 hi/lo)
    gemm_tc<<<dim3(3 * DMOD / 128, MROWS / 128), 256, GSMEM>>>(
        Axh, Axl, Bqh, Bql, nullptr, xwq, 3 * DMOD, DMOD, 0);
    gemm_tc<<<dim3(2 * DMOD / 128, MROWS / 128), 256, GSMEM>>>(
        Axh, Axl, Bhh, Bhl, nullptr, xwh, 2 * DMOD, DMOD, 0);

    // 2) head scatter + RoPE
    {
        int total = BB * HN * NSEQ * (DH / 2);
        scatter_rope_k<<<(total + 255) / 256, 256>>>(xwq, xwh, Q, K, V, HK, HV);
    }

    // 3) fused attention (fp32)
    attn_k<<<dim3(NSEQ / 64, BB * HN), 256, ASMEM>>>(Q, K, V, HK, HV, alpha, attn);

    // 4) output projection + bias on tensor cores
    packA_k<<<(MROWS * DMOD / 4 + 255) / 256, 256>>>(attn, Ath, Atl, MROWS * DMOD / 4);
    gemm_tc<<<dim3(DMOD / 128, MROWS / 128), 256, GSMEM>>>(
        Ath, Atl, Boh, Bol, b_out, out, DMOD, DMOD, 1);
}

// round 5
// speedup vs baseline: 2.2415x; 1.6560x over previous
#include <cuda_runtime.h>
#include <cuda_bf16.h>
#include <math.h>
#include <stdint.h>

// Problem constants
#define BB    2
#define NSEQ  2048
#define DMOD  1024
#define HN    16
#define DH    64
#define MROWS (BB*NSEQ)          // 4096
#define SCALE 0.125f             // Dh^-0.5

// ---------------- scratch (device globals: allocation-free) ----------------
__device__ __align__(256) float g_xw_qkv[(size_t)MROWS * 3 * DMOD];
__device__ __align__(256) float g_xw_hkv[(size_t)MROWS * 2 * DMOD];
__device__ __align__(256) float g_attn[(size_t)MROWS * DMOD];

// bf16 hi/lo head tensors [bh][n][64]
#define HT ((size_t)BB*HN*NSEQ*DH)
__device__ __align__(256) __nv_bfloat16 g_Qh[HT],  g_Ql[HT];
__device__ __align__(256) __nv_bfloat16 g_Kh[HT],  g_Kl[HT];
__device__ __align__(256) __nv_bfloat16 g_Vh[HT],  g_Vl[HT];
__device__ __align__(256) __nv_bfloat16 g_HKh[HT], g_HKl[HT];
__device__ __align__(256) __nv_bfloat16 g_HVh[HT], g_HVl[HT];

// packed bf16 GEMM operands
__device__ __align__(256) __nv_bfloat16 g_Axh[(size_t)MROWS * DMOD];
__device__ __align__(256) __nv_bfloat16 g_Axl[(size_t)MROWS * DMOD];
__device__ __align__(256) __nv_bfloat16 g_Ath[(size_t)MROWS * DMOD];
__device__ __align__(256) __nv_bfloat16 g_Atl[(size_t)MROWS * DMOD];
__device__ __align__(256) __nv_bfloat16 g_Bqh[(size_t)3 * DMOD * DMOD];
__device__ __align__(256) __nv_bfloat16 g_Bql[(size_t)3 * DMOD * DMOD];
__device__ __align__(256) __nv_bfloat16 g_Bhh[(size_t)2 * DMOD * DMOD];
__device__ __align__(256) __nv_bfloat16 g_Bhl[(size_t)2 * DMOD * DMOD];
__device__ __align__(256) __nv_bfloat16 g_Boh[(size_t)DMOD * DMOD];
__device__ __align__(256) __nv_bfloat16 g_Bol[(size_t)DMOD * DMOD];

// ======================= PTX helpers (compute_103-safe) ====================
__device__ __forceinline__ uint32_t smem_u32(const void* p) {
    uint32_t a;
    asm("{ .reg .u64 t; cvta.to.shared.u64 t, %1; cvt.u32.u64 %0, t; }" : "=r"(a) : "l"(p));
    return a;
}
__device__ __forceinline__ void cpasync16(uint32_t dst, const void* src) {
    asm volatile("cp.async.cg.shared.global [%0], [%1], 16;" :: "r"(dst), "l"(src));
}
__device__ __forceinline__ void cp_commit() {
    asm volatile("cp.async.commit_group;");
}
template<int N>
__device__ __forceinline__ void cp_wait() {
    asm volatile("cp.async.wait_group %0;" :: "n"(N));
}
__device__ __forceinline__ void ldsm4(uint32_t* r, uint32_t addr) {
    asm volatile("ldmatrix.sync.aligned.m8n8.x4.shared.b16 {%0,%1,%2,%3}, [%4];"
        : "=r"(r[0]), "=r"(r[1]), "=r"(r[2]), "=r"(r[3]) : "r"(addr));
}
__device__ __forceinline__ void ldsm4t(uint32_t* r, uint32_t addr) {
    asm volatile("ldmatrix.sync.aligned.m8n8.x4.trans.shared.b16 {%0,%1,%2,%3}, [%4];"
        : "=r"(r[0]), "=r"(r[1]), "=r"(r[2]), "=r"(r[3]) : "r"(addr));
}
__device__ __forceinline__ void mma_bf16(float* d, const uint32_t* a,
                                         uint32_t b0, uint32_t b1) {
    asm volatile("mma.sync.aligned.m16n8k16.row.col.f32.bf16.bf16.f32 "
        "{%0,%1,%2,%3}, {%4,%5,%6,%7}, {%8,%9}, {%0,%1,%2,%3};"
        : "+f"(d[0]), "+f"(d[1]), "+f"(d[2]), "+f"(d[3])
        : "r"(a[0]), "r"(a[1]), "r"(a[2]), "r"(a[3]), "r"(b0), "r"(b1));
}
__device__ __forceinline__ void pack_hilo(float a, float b, uint32_t& hr, uint32_t& lr2) {
    __nv_bfloat16 ah = __float2bfloat16(a), bh = __float2bfloat16(b);
    float ar = a - __bfloat162float(ah), br = b - __bfloat162float(bh);
    __nv_bfloat162 hp; hp.x = ah; hp.y = bh;
    __nv_bfloat162 lp; lp.x = __float2bfloat16(ar); lp.y = __float2bfloat16(br);
    hr = *(uint32_t*)&hp;
    lr2 = *(uint32_t*)&lp;
}

// ======================= pack kernels ======================================
__global__ __launch_bounds__(256) void packA_k(
    const float* __restrict__ A, __nv_bfloat16* __restrict__ hi,
    __nv_bfloat16* __restrict__ lo, int n4)
{
    int idx = blockIdx.x * blockDim.x + threadIdx.x;
    if (idx >= n4) return;
    float4 v = ((const float4*)A)[idx];
    __nv_bfloat16 h[4], l[4];
    float vv[4] = {v.x, v.y, v.z, v.w};
    #pragma unroll
    for (int i = 0; i < 4; i++) {
        h[i] = __float2bfloat16(vv[i]);
        l[i] = __float2bfloat16(vv[i] - __bfloat162float(h[i]));
    }
    ((uint2*)hi)[idx] = *(uint2*)h;
    ((uint2*)lo)[idx] = *(uint2*)l;
}

__global__ __launch_bounds__(256) void packB_k(
    const float* __restrict__ W, __nv_bfloat16* __restrict__ hi,
    __nv_bfloat16* __restrict__ lo, int K, int N)
{
    __shared__ float s[32][33];
    int n0 = blockIdx.x * 32, k0 = blockIdx.y * 32;
    int tx = threadIdx.x & 31, ty = threadIdx.x >> 5;
    #pragma unroll
    for (int i = 0; i < 4; i++) {
        int k = ty + i * 8;
        s[k][tx] = W[(size_t)(k0 + k) * N + n0 + tx];
    }
    __syncthreads();
    #pragma unroll
    for (int i = 0; i < 4; i++) {
        int nl = ty + i * 8;
        float v = s[tx][nl];
        __nv_bfloat16 h = __float2bfloat16(v);
        __nv_bfloat16 l = __float2bfloat16(v - __bfloat162float(h));
        size_t o = (size_t)(n0 + nl) * K + k0 + tx;
        hi[o] = h;
        lo[o] = l;
    }
}

// ======================= mma.sync bf16 GEMM (unchanged from R4) ============
#define GLDB   80
#define MATB   (128 * GLDB)
#define STAGEB (4 * MATB)
#define GSMEM  (2 * STAGEB)

__global__ __launch_bounds__(256) void gemm_tc(
    const __nv_bfloat16* __restrict__ Ahi, const __nv_bfloat16* __restrict__ Alo,
    const __nv_bfloat16* __restrict__ Bhi, const __nv_bfloat16* __restrict__ Blo,
    const float* __restrict__ bias, float* __restrict__ C,
    int N, int K, int hasBias)
{
    extern __shared__ char smraw[];
    const uint32_t sb = smem_u32(smraw);
    const int tid = threadIdx.x;
    const int lane = tid & 31, wid = tid >> 5;
    const int wm = wid >> 2;
    const int wn = wid & 3;

    const int bm = blockIdx.y * 128;
    const int bn = blockIdx.x * 128;

    const __nv_bfloat16* srcs[4] = {
        Ahi + (size_t)bm * K, Alo + (size_t)bm * K,
        Bhi + (size_t)bn * K, Blo + (size_t)bn * K };

    auto load_stage = [&](int st, int kc) {
        #pragma unroll
        for (int i = 0; i < 8; i++) {
            int idx = tid + i * 256;
            int mat = idx >> 9;
            int rem = idx & 511;
            int r = rem >> 2, ch = rem & 3;
            const __nv_bfloat16* g = srcs[mat] + (size_t)r * K + kc * 32 + ch * 8;
            cpasync16(sb + st * STAGEB + mat * MATB + r * GLDB + ch * 16, g);
        }
        cp_commit();
    };

    float acc[4][4][4];
    #pragma unroll
    for (int a = 0; a < 4; a++)
        #pragma unroll
        for (int b = 0; b < 4; b++)
            #pragma unroll
            for (int c = 0; c < 4; c++) acc[a][b][c] = 0.f;

    const int KC = K >> 5;
    load_stage(0, 0);

    const int arow = lane & 15;
    const int ahalf = (lane >> 4) << 3;

    for (int kc = 0; kc < KC; kc++) {
        int cur = kc & 1;
        if (kc + 1 < KC) load_stage(1 - cur, kc + 1);
        if (kc + 1 < KC) cp_wait<1>(); else cp_wait<0>();
        __syncthreads();

        #pragma unroll
        for (int kk = 0; kk < 32; kk += 16) {
            uint32_t ah[4][4], al[4][4], bh[2][4], bl[2][4];
            int acol = kk + ahalf;
            uint32_t stbase = sb + cur * STAGEB;
            #pragma unroll
            for (int mb = 0; mb < 4; mb++) {
                int r = wm * 64 + mb * 16 + arow;
                uint32_t ad = stbase + r * GLDB + acol * 2;
                ldsm4(ah[mb], ad);
                ldsm4(al[mb], ad + MATB);
            }
            #pragma unroll
            for (int p = 0; p < 2; p++) {
                int r = wn * 32 + p * 16 + arow;
                uint32_t bd = stbase + 2 * MATB + r * GLDB + acol * 2;
                ldsm4(bh[p], bd);
                ldsm4(bl[p], bd + MATB);
            }
            #pragma unroll
            for (int mb = 0; mb < 4; mb++)
                #pragma unroll
                for (int nb = 0; nb < 4; nb++) {
                    int p = nb >> 1, hf = nb & 1;
                    mma_bf16(acc[mb][nb], ah[mb], bh[p][hf], bh[p][hf + 2]);
                    mma_bf16(acc[mb][nb], ah[mb], bl[p][hf], bl[p][hf + 2]);
                    mma_bf16(acc[mb][nb], al[mb], bh[p][hf], bh[p][hf + 2]);
                }
        }
        __syncthreads();
    }

    #pragma unroll
    for (int mb = 0; mb < 4; mb++) {
        int r0 = bm + wm * 64 + mb * 16 + (lane >> 2);
        #pragma unroll
        for (int nb = 0; nb < 4; nb++) {
            int c0 = bn + wn * 32 + nb * 8 + (lane & 3) * 2;
            float bx = 0.f, by = 0.f;
            if (hasBias) { bx = bias[c0]; by = bias[c0 + 1]; }
            float2 v0 = { acc[mb][nb][0] + bx, acc[mb][nb][1] + by };
            float2 v1 = { acc[mb][nb][2] + bx, acc[mb][nb][3] + by };
            *(float2*)(C + (size_t)r0 * N + c0) = v0;
            *(float2*)(C + (size_t)(r0 + 8) * N + c0) = v1;
        }
    }
}

// ---------------- scatter to head layout + RoPE -> bf16 hi/lo --------------
__global__ __launch_bounds__(256) void scatter_rope_k(
    const float* __restrict__ xwq, const float* __restrict__ xwh,
    __nv_bfloat16* __restrict__ Qh, __nv_bfloat16* __restrict__ Ql,
    __nv_bfloat16* __restrict__ Kh, __nv_bfloat16* __restrict__ Kl,
    __nv_bfloat16* __restrict__ Vh, __nv_bfloat16* __restrict__ Vl,
    __nv_bfloat16* __restrict__ HKh, __nv_bfloat16* __restrict__ HKl,
    __nv_bfloat16* __restrict__ HVh, __nv_bfloat16* __restrict__ HVl)
{
    int idx = blockIdx.x * blockDim.x + threadIdx.x;
    const int total = BB * HN * NSEQ * (DH / 2);
    if (idx >= total) return;
    int i = idx & 31;
    int n = (idx >> 5) & (NSEQ - 1);
    int h = (idx >> 16) & (HN - 1);
    int b = idx >> 20;

    size_t row = (size_t)b * NSEQ + n;
    const float* xq = xwq + row * (3 * DMOD);
    const float* xh = xwh + row * (2 * DMOD);
    int col = h * DH + 2 * i;

    float q0 = xq[col],            q1 = xq[col + 1];
    float k0 = xq[DMOD + col],     k1 = xq[DMOD + col + 1];
    float v0 = xq[2 * DMOD + col], v1 = xq[2 * DMOD + col + 1];
    float hk0 = xh[col],           hk1 = xh[col + 1];
    float hv0 = xh[DMOD + col],    hv1 = xh[DMOD + col + 1];

    double freq = pow(10000.0, -(double)(2 * i) / 64.0);
    float ang = (float)((double)n * freq);
    float s, c;
    sincosf(ang, &s, &c);
    float qr0 = q0 * c - q1 * s, qr1 = q1 * c + q0 * s;
    float kr0 = k0 * c - k1 * s, kr1 = k1 * c + k0 * s;

    size_t o = (((size_t)(b * HN + h) * NSEQ) + n) * DH + 2 * i;

    auto st = [&](__nv_bfloat16* H, __nv_bfloat16* L, float a, float bb2) {
        __nv_bfloat16 ha = __float2bfloat16(a), hb = __float2bfloat16(bb2);
        __nv_bfloat162 hp; hp.x = ha; hp.y = hb;
        __nv_bfloat162 lp;
        lp.x = __float2bfloat16(a - __bfloat162float(ha));
        lp.y = __float2bfloat16(bb2 - __bfloat162float(hb));
        *(__nv_bfloat162*)(H + o) = hp;
        *(__nv_bfloat162*)(L + o) = lp;
    };
    st(Qh, Ql, qr0, qr1);
    st(Kh, Kl, kr0, kr1);
    st(Vh, Vl, v0, v1);
    st(HKh, HKl, hk0, hk1);
    st(HVh, HVl, hv0, hv1);
}

// ---------------- tensor-core flash attention ------------------------------
// CTA = 128 q-rows of one (b,h); 8 warps x 16 rows; k-tiles of 64.
// smem rows padded to 144 B (72 bf16) for conflict-free ldmatrix.
#define ARS   144
#define AQH   0
#define AQL   (1 * 128 * ARS)
#define AHKH  (2 * 128 * ARS)
#define AHKL  (3 * 128 * ARS)
#define AHVH  (4 * 128 * ARS)
#define AHVL  (5 * 128 * ARS)
#define AKH   (6 * 128 * ARS)
#define AKL   (AKH + 64 * ARS)
#define AVH   (AKH + 2 * 64 * ARS)
#define AVL   (AKH + 3 * 64 * ARS)
#define ATT_SMEM (AKH + 4 * 64 * ARS)   // 147456

__global__ __launch_bounds__(256) void attn_mma(
    const __nv_bfloat16* __restrict__ Qh, const __nv_bfloat16* __restrict__ Ql,
    const __nv_bfloat16* __restrict__ Kh, const __nv_bfloat16* __restrict__ Kl,
    const __nv_bfloat16* __restrict__ Vh, const __nv_bfloat16* __restrict__ Vl,
    const __nv_bfloat16* __restrict__ HKh, const __nv_bfloat16* __restrict__ HKl,
    const __nv_bfloat16* __restrict__ HVh, const __nv_bfloat16* __restrict__ HVl,
    const float* __restrict__ alpha, float* __restrict__ Out)
{
    extern __shared__ char smraw[];
    const uint32_t sb = smem_u32(smraw);
    const int tid = threadIdx.x, lane = tid & 31, w = tid >> 5;
    const int bh = blockIdx.x;
    const int qt = (NSEQ / 128 - 1) - blockIdx.y;   // biggest tiles first
    const int h = bh & (HN - 1), b = bh >> 4;
    const size_t gbase = (size_t)bh * NSEQ * DH;
    const float NEGINF = __int_as_float(0xff800000);

    // ---- prologue: Q/HK/HV hi/lo tiles ----
    {
        const size_t qoff = gbase + (size_t)qt * 128 * DH;
        const __nv_bfloat16* ap[6] = { Qh + qoff, Ql + qoff, HKh + qoff,
                                       HKl + qoff, HVh + qoff, HVl + qoff };
        #pragma unroll
        for (int i = 0; i < 24; i++) {
            int idx = tid + i * 256;
            int arr = idx >> 10, rem = idx & 1023;
            int row = rem >> 3, ch = rem & 7;
            cpasync16(sb + arr * (128 * ARS) + row * ARS + ch * 16,
                      ap[arr] + row * DH + ch * 8);
        }
        cp_commit(); cp_wait<0>();
    }
    __syncthreads();

    // ---- qhk per row (2 rows/thread) ----
    const int lr = w * 16 + (lane >> 2);
    float qhk[2];
    {
        const int d0 = (lane & 3) * 16;
        #pragma unroll
        for (int ri = 0; ri < 2; ri++) {
            int rr = lr + 8 * ri;
            float s = 0.f;
            #pragma unroll
            for (int dd = 0; dd < 16; dd++) {
                int d = d0 + dd;
                float qv = __bfloat162float(*(__nv_bfloat16*)(smraw + AQH + rr * ARS + d * 2))
                         + __bfloat162float(*(__nv_bfloat16*)(smraw + AQL + rr * ARS + d * 2));
                float kv = __bfloat162float(*(__nv_bfloat16*)(smraw + AHKH + rr * ARS + d * 2))
                         + __bfloat162float(*(__nv_bfloat16*)(smraw + AHKL + rr * ARS + d * 2));
                s = fmaf(qv, kv, s);
            }
            s += __shfl_xor_sync(0xffffffffu, s, 1);
            s += __shfl_xor_sync(0xffffffffu, s, 2);
            qhk[ri] = s;
        }
    }

    const float sigA = 1.f / (1.f + __expf(-alpha[h]));
    float rmax[2] = {NEGINF, NEGINF}, lsum[2] = {0.f, 0.f}, accm[2] = {0.f, 0.f};
    float acco[8][4];
    #pragma unroll
    for (int nb = 0; nb < 8; nb++)
        #pragma unroll
        for (int e = 0; e < 4; e++) acco[nb][e] = 0.f;

    const int ktend = 2 * qt + 1;
    for (int kt = 0; kt <= ktend; kt++) {
        __syncthreads();
        {
            const size_t koff = gbase + (size_t)kt * 64 * DH;
            const __nv_bfloat16* kp[4] = { Kh + koff, Kl + koff, Vh + koff, Vl + koff };
            #pragma unroll
            for (int i = 0; i < 8; i++) {
                int idx = tid + i * 256;
                int arr = idx >> 9, rem = idx & 511;
                int row = rem >> 3, ch = rem & 7;
                cpasync16(sb + AKH + arr * (64 * ARS) + row * ARS + ch * 16,
                          kp[arr] + row * DH + ch * 8);
            }
            cp_commit(); cp_wait<0>();
        }
        __syncthreads();

        float S1[8][4], S2[8][4], S3[8][4];
        #pragma unroll
        for (int nb = 0; nb < 8; nb++)
            #pragma unroll
            for (int e = 0; e < 4; e++) { S1[nb][e] = 0.f; S2[nb][e] = 0.f; S3[nb][e] = 0.f; }

        #pragma unroll
        for (int ks = 0; ks < 4; ks++) {
            uint32_t aQh[4], aQl[4], aKh2[4], aKl2[4], aVh2[4], aVl2[4];
            uint32_t abase = sb + (w * 16 + (lane & 15)) * ARS + ((lane >> 4) + 2 * ks) * 16;
            ldsm4(aQh,  abase + AQH);
            ldsm4(aQl,  abase + AQL);
            ldsm4(aKh2, abase + AHKH);
            ldsm4(aKl2, abase + AHKL);
            ldsm4(aVh2, abase + AHVH);
            ldsm4(aVl2, abase + AHVL);
            #pragma unroll
            for (int np = 0; np < 4; np++) {
                uint32_t bKh[4], bKl[4], bVh[4], bVl[4];
                uint32_t bbase = sb + (np * 16 + (lane & 15)) * ARS + ((lane >> 4) + 2 * ks) * 16;
                ldsm4(bKh, bbase + AKH);
                ldsm4(bKl, bbase + AKL);
                ldsm4(bVh, bbase + AVH);
                ldsm4(bVl, bbase + AVL);
                #pragma unroll
                for (int hf = 0; hf < 2; hf++) {
                    int nb = np * 2 + hf;
                    mma_bf16(S1[nb], aQh,  bKh[hf], bKh[hf + 2]);
                    mma_bf16(S1[nb], aQh,  bKl[hf], bKl[hf + 2]);
                    mma_bf16(S1[nb], aQl,  bKh[hf], bKh[hf + 2]);
                    mma_bf16(S2[nb], aKh2, bKh[hf], bKh[hf + 2]);
                    mma_bf16(S2[nb], aKh2, bKl[hf], bKl[hf + 2]);
                    mma_bf16(S2[nb], aKl2, bKh[hf], bKh[hf + 2]);
                    mma_bf16(S3[nb], aVh2, bVh[hf], bVh[hf + 2]);
                    mma_bf16(S3[nb], aVh2, bVl[hf], bVl[hf + 2]);
                    mma_bf16(S3[nb], aVl2, bVh[hf], bVh[hf + 2]);
                }
            }
        }

        // ---- softmax with silu-modulated scores ----
        const bool needmask = (kt >= 2 * qt);
        float tmax[2] = {NEGINF, NEGINF};
        #pragma unroll
        for (int nb = 0; nb < 8; nb++)
            #pragma unroll
            for (int e = 0; e < 4; e++) {
                int ri = e >> 1;
                float z = S2[nb][e] * qhk[ri] * SCALE;
                float sil = z / (1.f + __expf(-z));
                float s = S1[nb][e] * SCALE - sil;
                if (needmask) {
                    int colg = kt * 64 + nb * 8 + (lane & 3) * 2 + (e & 1);
                    int rowg = qt * 128 + lr + 8 * ri;
                    if (colg > rowg) s = NEGINF;
                }
                S1[nb][e] = s;
                tmax[ri] = fmaxf(tmax[ri], s);
            }
        float scv[2];
        #pragma unroll
        for (int ri = 0; ri < 2; ri++) {
            float t = tmax[ri];
            t = fmaxf(t, __shfl_xor_sync(0xffffffffu, t, 1));
            t = fmaxf(t, __shfl_xor_sync(0xffffffffu, t, 2));
            float nm = fmaxf(rmax[ri], t);
            float sc = __expf(rmax[ri] - nm);
            rmax[ri] = nm;
            lsum[ri] *= sc; accm[ri] *= sc;
            scv[ri] = sc;
        }
        #pragma unroll
        for (int nb = 0; nb < 8; nb++) {
            acco[nb][0] *= scv[0]; acco[nb][1] *= scv[0];
            acco[nb][2] *= scv[1]; acco[nb][3] *= scv[1];
        }
        #pragma unroll
        for (int nb = 0; nb < 8; nb++)
            #pragma unroll
            for (int e = 0; e < 4; e++) {
                int ri = e >> 1;
                float p = __expf(S1[nb][e] - rmax[ri]);
                S1[nb][e] = p;
                lsum[ri] += p;
                accm[ri] = fmaf(p, S3[nb][e], accm[ri]);
            }

        // ---- acco += P @ V (P from registers, V^T via ldmatrix.trans) ----
        #pragma unroll
        for (int ks = 0; ks < 4; ks++) {
            uint32_t Ph[4], Pl[4];
            pack_hilo(S1[2 * ks][0],     S1[2 * ks][1],     Ph[0], Pl[0]);
            pack_hilo(S1[2 * ks][2],     S1[2 * ks][3],     Ph[1], Pl[1]);
            pack_hilo(S1[2 * ks + 1][0], S1[2 * ks + 1][1], Ph[2], Pl[2]);
            pack_hilo(S1[2 * ks + 1][2], S1[2 * ks + 1][3], Ph[3], Pl[3]);
            #pragma unroll
            for (int np = 0; np < 4; np++) {
                uint32_t tVh[4], tVl[4];
                uint32_t tb2 = sb + (ks * 16 + (lane & 7) + ((lane >> 4) & 1) * 8) * ARS
                             + (np * 2 + ((lane >> 3) & 1)) * 16;
                ldsm4t(tVh, tb2 + AVH);
                ldsm4t(tVl, tb2 + AVL);
                #pragma unroll
                for (int hf = 0; hf < 2; hf++) {
                    int nb = np * 2 + hf;
                    mma_bf16(acco[nb], Ph, tVh[hf], tVh[hf + 2]);
                    mma_bf16(acco[nb], Ph, tVl[hf], tVl[hf + 2]);
                    mma_bf16(acco[nb], Pl, tVh[hf], tVh[hf + 2]);
                }
            }
        }
    }

    // ---- final reduction + epilogue ----
    float inv[2], mo[2];
    #pragma unroll
    for (int ri = 0; ri < 2; ri++) {
        float lv = lsum[ri], mv = accm[ri];
        lv += __shfl_xor_sync(0xffffffffu, lv, 1);
        lv += __shfl_xor_sync(0xffffffffu, lv, 2);
        mv += __shfl_xor_sync(0xffffffffu, mv, 1);
        mv += __shfl_xor_sync(0xffffffffu, mv, 2);
        inv[ri] = 1.f / lv;
        mo[ri] = mv * inv[ri] * sigA;
    }
    #pragma unroll
    for (int nb = 0; nb < 8; nb++) {
        int d0 = nb * 8 + (lane & 3) * 2;
        #pragma unroll
        for (int ri = 0; ri < 2; ri++) {
            int rl = lr + 8 * ri;
            __nv_bfloat162 hvh = *(__nv_bfloat162*)(smraw + AHVH + rl * ARS + d0 * 2);
            __nv_bfloat162 hvl = *(__nv_bfloat162*)(smraw + AHVL + rl * ARS + d0 * 2);
            float hv0 = __bfloat162float(hvh.x) + __bfloat162float(hvl.x);
            float hv1 = __bfloat162float(hvh.y) + __bfloat162float(hvl.y);
            float2 o;
            o.x = acco[nb][2 * ri + 0] * inv[ri] - mo[ri] * hv0;
            o.y = acco[nb][2 * ri + 1] * inv[ri] - mo[ri] * hv1;
            size_t go = ((size_t)(b * NSEQ + qt * 128 + rl)) * DMOD + h * DH + d0;
            *(float2*)(Out + go) = o;
        }
    }
}

// ---------------- launcher --------------------------------------------------
extern "C" void kernel_launch(void* const* d_in, const int* in_sizes, int n_in,
                              void* d_out, int out_size)
{
    const float* x     = (const float*)d_in[0];
    const float* w_qkv = (const float*)d_in[1];
    const float* w_hkv = (const float*)d_in[2];
    const float* w_out = (const float*)d_in[3];
    const float* b_out = (const float*)d_in[4];
    const float* alpha = (const float*)d_in[5];
    float* out = (float*)d_out;

    float *xwq, *xwh, *attn;
    __nv_bfloat16 *Qh,*Ql,*Kh,*Kl,*Vh,*Vl,*HKh,*HKl,*HVh,*HVl;
    __nv_bfloat16 *Axh, *Axl, *Ath, *Atl, *Bqh, *Bql, *Bhh, *Bhl, *Boh, *Bol;
    cudaGetSymbolAddress((void**)&xwq,  g_xw_qkv);
    cudaGetSymbolAddress((void**)&xwh,  g_xw_hkv);
    cudaGetSymbolAddress((void**)&attn, g_attn);
    cudaGetSymbolAddress((void**)&Qh,   g_Qh);
    cudaGetSymbolAddress((void**)&Ql,   g_Ql);
    cudaGetSymbolAddress((void**)&Kh,   g_Kh);
    cudaGetSymbolAddress((void**)&Kl,   g_Kl);
    cudaGetSymbolAddress((void**)&Vh,   g_Vh);
    cudaGetSymbolAddress((void**)&Vl,   g_Vl);
    cudaGetSymbolAddress((void**)&HKh,  g_HKh);
    cudaGetSymbolAddress((void**)&HKl,  g_HKl);
    cudaGetSymbolAddress((void**)&HVh,  g_HVh);
    cudaGetSymbolAddress((void**)&HVl,  g_HVl);
    cudaGetSymbolAddress((void**)&Axh,  g_Axh);
    cudaGetSymbolAddress((void**)&Axl,  g_Axl);
    cudaGetSymbolAddress((void**)&Ath,  g_Ath);
    cudaGetSymbolAddress((void**)&Atl,  g_Atl);
    cudaGetSymbolAddress((void**)&Bqh,  g_Bqh);
    cudaGetSymbolAddress((void**)&Bql,  g_Bql);
    cudaGetSymbolAddress((void**)&Bhh,  g_Bhh);
    cudaGetSymbolAddress((void**)&Bhl,  g_Bhl);
    cudaGetSymbolAddress((void**)&Boh,  g_Boh);
    cudaGetSymbolAddress((void**)&Bol,  g_Bol);

    cudaFuncSetAttribute(gemm_tc, cudaFuncAttributeMaxDynamicSharedMemorySize, GSMEM);
    cudaFuncSetAttribute(attn_mma, cudaFuncAttributeMaxDynamicSharedMemorySize, ATT_SMEM);

    // 0) pack GEMM operands
    packA_k<<<(MROWS * DMOD / 4 + 255) / 256, 256>>>(x, Axh, Axl, MROWS * DMOD / 4);
    packB_k<<<dim3(3 * DMOD / 32, DMOD / 32), 256>>>(w_qkv, Bqh, Bql, DMOD, 3 * DMOD);
    packB_k<<<dim3(2 * DMOD / 32, DMOD / 32), 256>>>(w_hkv, Bhh, Bhl, DMOD, 2 * DMOD);
    packB_k<<<dim3(DMOD / 32, DMOD / 32), 256>>>(w_out, Boh, Bol, DMOD, DMOD);

    // 1) projections
    gemm_tc<<<dim3(3 * DMOD / 128, MROWS / 128), 256, GSMEM>>>(
        Axh, Axl, Bqh, Bql, nullptr, xwq, 3 * DMOD, DMOD, 0);
    gemm_tc<<<dim3(2 * DMOD / 128, MROWS / 128), 256, GSMEM>>>(
        Axh, Axl, Bhh, Bhl, nullptr, xwh, 2 * DMOD, DMOD, 0);

    // 2) head scatter + RoPE -> bf16 hi/lo
    {
        int total = BB * HN * NSEQ * (DH / 2);
        scatter_rope_k<<<(total + 255) / 256, 256>>>(
            xwq, xwh, Qh, Ql, Kh, Kl, Vh, Vl, HKh, HKl, HVh, HVl);
    }

    // 3) tensor-core flash attention
    attn_mma<<<dim3(BB * HN, NSEQ / 128), 256, ATT_SMEM>>>(
        Qh, Ql, Kh, Kl, Vh, Vl, HKh, HKl, HVh, HVl, alpha, attn);

    // 4) output projection + bias
    packA_k<<<(MROWS * DMOD / 4 + 255) / 256, 256>>>(attn, Ath, Atl, MROWS * DMOD / 4);
    gemm_tc<<<dim3(DMOD / 128, MROWS / 128), 256, GSMEM>>>(
        Ath, Atl, Boh, Bol, b_out, out, DMOD, DMOD, 1);
}

// round 8
// speedup vs baseline: 2.3502x; 1.0485x over previous
#include <cuda_runtime.h>
#include <cuda_bf16.h>
#include <math.h>
#include <stdint.h>

// Problem constants
#define BB    2
#define NSEQ  2048
#define DMOD  1024
#define HN    16
#define DH    64
#define MROWS (BB*NSEQ)          // 4096
#define SCALE 0.125f             // Dh^-0.5

// ---------------- scratch (device globals: allocation-free) ----------------
__device__ __align__(256) float g_xw_qkv[(size_t)MROWS * 3 * DMOD];
__device__ __align__(256) float g_xw_hkv[(size_t)MROWS * 2 * DMOD];

// bf16 hi/lo head tensors [bh][n][64]
#define HT ((size_t)BB*HN*NSEQ*DH)
__device__ __align__(256) __nv_bfloat16 g_Qh[HT],  g_Ql[HT];
__device__ __align__(256) __nv_bfloat16 g_Kh[HT],  g_Kl[HT];
__device__ __align__(256) __nv_bfloat16 g_Vh[HT],  g_Vl[HT];
__device__ __align__(256) __nv_bfloat16 g_HKh[HT], g_HKl[HT];
__device__ __align__(256) __nv_bfloat16 g_HVh[HT], g_HVl[HT];

// packed bf16 GEMM operands
__device__ __align__(256) __nv_bfloat16 g_Axh[(size_t)MROWS * DMOD];
__device__ __align__(256) __nv_bfloat16 g_Axl[(size_t)MROWS * DMOD];
__device__ __align__(256) __nv_bfloat16 g_Ath[(size_t)MROWS * DMOD];   // attn out hi
__device__ __align__(256) __nv_bfloat16 g_Atl[(size_t)MROWS * DMOD];   // attn out lo
__device__ __align__(256) __nv_bfloat16 g_Bqh[(size_t)3 * DMOD * DMOD];
__device__ __align__(256) __nv_bfloat16 g_Bql[(size_t)3 * DMOD * DMOD];
__device__ __align__(256) __nv_bfloat16 g_Bhh[(size_t)2 * DMOD * DMOD];
__device__ __align__(256) __nv_bfloat16 g_Bhl[(size_t)2 * DMOD * DMOD];
__device__ __align__(256) __nv_bfloat16 g_Boh[(size_t)DMOD * DMOD];
__device__ __align__(256) __nv_bfloat16 g_Bol[(size_t)DMOD * DMOD];

// ======================= PTX helpers (compute_103-safe) ====================
__device__ __forceinline__ uint32_t smem_u32(const void* p) {
    uint32_t a;
    asm("{ .reg .u64 t; cvta.to.shared.u64 t, %1; cvt.u32.u64 %0, t; }" : "=r"(a) : "l"(p));
    return a;
}
__device__ __forceinline__ void cpasync16(uint32_t dst, const void* src) {
    asm volatile("cp.async.cg.shared.global [%0], [%1], 16;" :: "r"(dst), "l"(src));
}
__device__ __forceinline__ void cp_commit() {
    asm volatile("cp.async.commit_group;");
}
template<int N>
__device__ __forceinline__ void cp_wait() {
    asm volatile("cp.async.wait_group %0;" :: "n"(N));
}
__device__ __forceinline__ void ldsm4(uint32_t* r, uint32_t addr) {
    asm volatile("ldmatrix.sync.aligned.m8n8.x4.shared.b16 {%0,%1,%2,%3}, [%4];"
        : "=r"(r[0]), "=r"(r[1]), "=r"(r[2]), "=r"(r[3]) : "r"(addr));
}
__device__ __forceinline__ void ldsm4t(uint32_t* r, uint32_t addr) {
    asm volatile("ldmatrix.sync.aligned.m8n8.x4.trans.shared.b16 {%0,%1,%2,%3}, [%4];"
        : "=r"(r[0]), "=r"(r[1]), "=r"(r[2]), "=r"(r[3]) : "r"(addr));
}
__device__ __forceinline__ void mma_bf16(float* d, const uint32_t* a,
                                         uint32_t b0, uint32_t b1) {
    asm volatile("mma.sync.aligned.m16n8k16.row.col.f32.bf16.bf16.f32 "
        "{%0,%1,%2,%3}, {%4,%5,%6,%7}, {%8,%9}, {%0,%1,%2,%3};"
        : "+f"(d[0]), "+f"(d[1]), "+f"(d[2]), "+f"(d[3])
        : "r"(a[0]), "r"(a[1]), "r"(a[2]), "r"(a[3]), "r"(b0), "r"(b1));
}
__device__ __forceinline__ void pack_hilo(float a, float b, uint32_t& hr, uint32_t& lr2) {
    __nv_bfloat16 ah = __float2bfloat16(a), bh = __float2bfloat16(b);
    float ar = a - __bfloat162float(ah), br = b - __bfloat162float(bh);
    __nv_bfloat162 hp; hp.x = ah; hp.y = bh;
    __nv_bfloat162 lp; lp.x = __float2bfloat16(ar); lp.y = __float2bfloat16(br);
    hr = *(uint32_t*)&hp;
    lr2 = *(uint32_t*)&lp;
}

// ======================= pack kernels ======================================
__global__ __launch_bounds__(256) void packA_k(
    const float* __restrict__ A, __nv_bfloat16* __restrict__ hi,
    __nv_bfloat16* __restrict__ lo, int n4)
{
    int idx = blockIdx.x * blockDim.x + threadIdx.x;
    if (idx >= n4) return;
    float4 v = ((const float4*)A)[idx];
    __nv_bfloat16 h[4], l[4];
    float vv[4] = {v.x, v.y, v.z, v.w};
    #pragma unroll
    for (int i = 0; i < 4; i++) {
        h[i] = __float2bfloat16(vv[i]);
        l[i] = __float2bfloat16(vv[i] - __bfloat162float(h[i]));
    }
    ((uint2*)hi)[idx] = *(uint2*)h;
    ((uint2*)lo)[idx] = *(uint2*)l;
}

__global__ __launch_bounds__(256) void packB_k(
    const float* __restrict__ W, __nv_bfloat16* __restrict__ hi,
    __nv_bfloat16* __restrict__ lo, int K, int N)
{
    __shared__ float s[32][33];
    int n0 = blockIdx.x * 32, k0 = blockIdx.y * 32;
    int tx = threadIdx.x & 31, ty = threadIdx.x >> 5;
    #pragma unroll
    for (int i = 0; i < 4; i++) {
        int k = ty + i * 8;
        s[k][tx] = W[(size_t)(k0 + k) * N + n0 + tx];
    }
    __syncthreads();
    #pragma unroll
    for (int i = 0; i < 4; i++) {
        int nl = ty + i * 8;
        float v = s[tx][nl];
        __nv_bfloat16 h = __float2bfloat16(v);
        __nv_bfloat16 l = __float2bfloat16(v - __bfloat162float(h));
        size_t o = (size_t)(n0 + nl) * K + k0 + tx;
        hi[o] = h;
        lo[o] = l;
    }
}

// ======================= mma.sync bf16 GEMM ================================
// CTA: 128x128 tile, BK=32, 128 threads = 4 warps (2x2), warp tile 64x64.
// Dual-output: blocks with bx < nx1 compute C1 (B1), others C2 (B2).
#define GLDB   80
#define MATB   (128 * GLDB)            // 10240
#define STAGEB (4 * MATB)              // 40960
#define GSMEM  (2 * STAGEB)            // 81920

__global__ __launch_bounds__(128) void gemm_tc(
    const __nv_bfloat16* __restrict__ Ahi, const __nv_bfloat16* __restrict__ Alo,
    const __nv_bfloat16* __restrict__ B1h, const __nv_bfloat16* __restrict__ B1l,
    const __nv_bfloat16* __restrict__ B2h, const __nv_bfloat16* __restrict__ B2l,
    const float* __restrict__ bias,
    float* __restrict__ C1, float* __restrict__ C2,
    int N1, int N2, int K, int nx1, int hasBias)
{
    extern __shared__ char smraw[];
    const uint32_t sb = smem_u32(smraw);
    const int tid = threadIdx.x;
    const int lane = tid & 31, wid = tid >> 5;
    const int wm = wid >> 1;          // 0..1
    const int wn = wid & 1;           // 0..1

    const int bm = blockIdx.y * 128;
    const __nv_bfloat16 *Bh_, *Bl_;
    float* C;
    int N, bn;
    if ((int)blockIdx.x < nx1) {
        Bh_ = B1h; Bl_ = B1l; C = C1; N = N1; bn = blockIdx.x * 128;
    } else {
        Bh_ = B2h; Bl_ = B2l; C = C2; N = N2; bn = (blockIdx.x - nx1) * 128;
    }

    const __nv_bfloat16* srcs[4] = {
        Ahi + (size_t)bm * K, Alo + (size_t)bm * K,
        Bh_ + (size_t)bn * K, Bl_ + (size_t)bn * K };

    auto load_stage = [&](int st, int kc) {
        #pragma unroll
        for (int i = 0; i < 16; i++) {
            int idx = tid + i * 128;
            int mat = idx >> 9;
            int rem = idx & 511;
            int r = rem >> 2, ch = rem & 3;
            cpasync16(sb + st * STAGEB + mat * MATB + r * GLDB + ch * 16,
                      srcs[mat] + (size_t)r * K + kc * 32 + ch * 8);
        }
        cp_commit();
    };

    float acc[4][8][4];
    #pragma unroll
    for (int a = 0; a < 4; a++)
        #pragma unroll
        for (int b = 0; b < 8; b++)
            #pragma unroll
            for (int c = 0; c < 4; c++) acc[a][b][c] = 0.f;

    const int KC = K >> 5;
    load_stage(0, 0);

    const int arow = lane & 15;
    const int ahalf = (lane >> 4) << 3;

    for (int kc = 0; kc < KC; kc++) {
        int cur = kc & 1;
        if (kc + 1 < KC) load_stage(1 - cur, kc + 1);
        if (kc + 1 < KC) cp_wait<1>(); else cp_wait<0>();
        __syncthreads();

        #pragma unroll
        for (int kk = 0; kk < 32; kk += 16) {
            uint32_t ah[4][4], al[4][4];
            int acol = kk + ahalf;
            uint32_t stb = sb + cur * STAGEB;
            #pragma unroll
            for (int mb = 0; mb < 4; mb++) {
                uint32_t ad = stb + (wm * 64 + mb * 16 + arow) * GLDB + acol * 2;
                ldsm4(ah[mb], ad);
                ldsm4(al[mb], ad + MATB);
            }
            #pragma unroll
            for (int np = 0; np < 4; np++) {
                uint32_t bh[4], bl[4];
                uint32_t bd = stb + 2 * MATB + (wn * 64 + np * 16 + arow) * GLDB + acol * 2;
                ldsm4(bh, bd);
                ldsm4(bl, bd + MATB);
                #pragma unroll
                for (int mb = 0; mb < 4; mb++)
                    #pragma unroll
                    for (int hf = 0; hf < 2; hf++) {
                        int nb = np * 2 + hf;
                        mma_bf16(acc[mb][nb], ah[mb], bh[hf], bh[hf + 2]);
                        mma_bf16(acc[mb][nb], ah[mb], bl[hf], bl[hf + 2]);
                        mma_bf16(acc[mb][nb], al[mb], bh[hf], bh[hf + 2]);
                    }
            }
        }
        __syncthreads();
    }

    #pragma unroll
    for (int mb = 0; mb < 4; mb++) {
        int r0 = bm + wm * 64 + mb * 16 + (lane >> 2);
        #pragma unroll
        for (int nb = 0; nb < 8; nb++) {
            int c0 = bn + wn * 64 + nb * 8 + (lane & 3) * 2;
            float bx = 0.f, by = 0.f;
            if (hasBias) { bx = bias[c0]; by = bias[c0 + 1]; }
            float2 v0 = { acc[mb][nb][0] + bx, acc[mb][nb][1] + by };
            float2 v1 = { acc[mb][nb][2] + bx, acc[mb][nb][3] + by };
            *(float2*)(C + (size_t)r0 * N + c0) = v0;
            *(float2*)(C + (size_t)(r0 + 8) * N + c0) = v1;
        }
    }
}

// ---------------- scatter to head layout + RoPE -> bf16 hi/lo --------------
__global__ __launch_bounds__(256) void scatter_rope_k(
    const float* __restrict__ xwq, const float* __restrict__ xwh,
    __nv_bfloat16* __restrict__ Qh, __nv_bfloat16* __restrict__ Ql,
    __nv_bfloat16* __restrict__ Kh, __nv_bfloat16* __restrict__ Kl,
    __nv_bfloat16* __restrict__ Vh, __nv_bfloat16* __restrict__ Vl,
    __nv_bfloat16* __restrict__ HKh, __nv_bfloat16* __restrict__ HKl,
    __nv_bfloat16* __restrict__ HVh, __nv_bfloat16* __restrict__ HVl)
{
    int idx = blockIdx.x * blockDim.x + threadIdx.x;
    const int total = BB * HN * NSEQ * (DH / 2);
    if (idx >= total) return;
    int i = idx & 31;
    int n = (idx >> 5) & (NSEQ - 1);
    int h = (idx >> 16) & (HN - 1);
    int b = idx >> 20;

    size_t row = (size_t)b * NSEQ + n;
    const float* xq = xwq + row * (3 * DMOD);
    const float* xh = xwh + row * (2 * DMOD);
    int col = h * DH + 2 * i;

    float q0 = xq[col],            q1 = xq[col + 1];
    float k0 = xq[DMOD + col],     k1 = xq[DMOD + col + 1];
    float v0 = xq[2 * DMOD + col], v1 = xq[2 * DMOD + col + 1];
    float hk0 = xh[col],           hk1 = xh[col + 1];
    float hv0 = xh[DMOD + col],    hv1 = xh[DMOD + col + 1];

    double freq = pow(10000.0, -(double)(2 * i) / 64.0);
    float ang = (float)((double)n * freq);
    float s, c;
    sincosf(ang, &s, &c);
    float qr0 = q0 * c - q1 * s, qr1 = q1 * c + q0 * s;
    float kr0 = k0 * c - k1 * s, kr1 = k1 * c + k0 * s;

    size_t o = (((size_t)(b * HN + h) * NSEQ) + n) * DH + 2 * i;

    auto st = [&](__nv_bfloat16* H, __nv_bfloat16* L, float a, float bb2) {
        __nv_bfloat16 ha = __float2bfloat16(a), hb = __float2bfloat16(bb2);
        __nv_bfloat162 hp; hp.x = ha; hp.y = hb;
        __nv_bfloat162 lp;
        lp.x = __float2bfloat16(a - __bfloat162float(ha));
        lp.y = __float2bfloat16(bb2 - __bfloat162float(hb));
        *(__nv_bfloat162*)(H + o) = hp;
        *(__nv_bfloat162*)(L + o) = lp;
    };
    st(Qh, Ql, qr0, qr1);
    st(Kh, Kl, kr0, kr1);
    st(Vh, Vl, v0, v1);
    st(HKh, HKl, hk0, hk1);
    st(HVh, HVl, hv0, hv1);
}

// ---------------- tensor-core flash attention ------------------------------
// CTA = 128 q-rows of one (b,h); 8 warps x 16 rows; k-tiles of 64,
// K/V tiles double-buffered (2-stage cp.async ring).
#define ARS   144
#define AQH   0
#define AQL   (1 * 128 * ARS)
#define AHKH  (2 * 128 * ARS)
#define AHKL  (3 * 128 * ARS)
#define AHVH  (4 * 128 * ARS)
#define AHVL  (5 * 128 * ARS)
#define AKV   (6 * 128 * ARS)          // 110592: KV ring base
#define KVS   (4 * 64 * ARS)           // 36864 per stage
#define KOFF_KH 0
#define KOFF_KL (64 * ARS)
#define KOFF_VH (2 * 64 * ARS)
#define KOFF_VL (3 * 64 * ARS)
#define ATT_SMEM (AKV + 2 * KVS)       // 184320

__global__ __launch_bounds__(256) void attn_mma(
    const __nv_bfloat16* __restrict__ Qh, const __nv_bfloat16* __restrict__ Ql,
    const __nv_bfloat16* __restrict__ Kh, const __nv_bfloat16* __restrict__ Kl,
    const __nv_bfloat16* __restrict__ Vh, const __nv_bfloat16* __restrict__ Vl,
    const __nv_bfloat16* __restrict__ HKh, const __nv_bfloat16* __restrict__ HKl,
    const __nv_bfloat16* __restrict__ HVh, const __nv_bfloat16* __restrict__ HVl,
    const float* __restrict__ alpha,
    __nv_bfloat16* __restrict__ Oh, __nv_bfloat16* __restrict__ Ol)
{
    extern __shared__ char smraw[];
    const uint32_t sb = smem_u32(smraw);
    const int tid = threadIdx.x, lane = tid & 31, w = tid >> 5;
    const int bh = blockIdx.x;
    const int qt = (NSEQ / 128 - 1) - blockIdx.y;   // biggest tiles first
    const int h = bh & (HN - 1), b = bh >> 4;
    const size_t gbase = (size_t)bh * NSEQ * DH;
    const float NEGINF = __int_as_float(0xff800000);
    const int ktend = 2 * qt + 1;

    auto kv_load = [&](int kt, int stage) {
        const size_t koff = gbase + (size_t)kt * 64 * DH;
        const __nv_bfloat16* kp[4] = { Kh + koff, Kl + koff, Vh + koff, Vl + koff };
        #pragma unroll
        for (int i = 0; i < 8; i++) {
            int idx = tid + i * 256;
            int arr = idx >> 9, rem = idx & 511;
            int row = rem >> 3, ch = rem & 7;
            cpasync16(sb + AKV + stage * KVS + arr * (64 * ARS) + row * ARS + ch * 16,
                      kp[arr] + row * DH + ch * 8);
        }
        cp_commit();
    };

    // ---- prologue: Q/HK/HV tiles + first two KV tiles ----
    {
        const size_t qoff = gbase + (size_t)qt * 128 * DH;
        const __nv_bfloat16* ap[6] = { Qh + qoff, Ql + qoff, HKh + qoff,
                                       HKl + qoff, HVh + qoff, HVl + qoff };
        #pragma unroll
        for (int i = 0; i < 24; i++) {
            int idx = tid + i * 256;
            int arr = idx >> 10, rem = idx & 1023;
            int row = rem >> 3, ch = rem & 7;
            cpasync16(sb + arr * (128 * ARS) + row * ARS + ch * 16,
                      ap[arr] + row * DH + ch * 8);
        }
        cp_commit();
    }
    kv_load(0, 0);
    kv_load(1, 1);          // ktend >= 1 always
    cp_wait<2>();           // Q/HK/HV complete
    __syncthreads();

    // ---- qhk per row (2 rows/thread) ----
    const int lr = w * 16 + (lane >> 2);
    float qhk[2];
    {
        const int d0 = (lane & 3) * 16;
        #pragma unroll
        for (int ri = 0; ri < 2; ri++) {
            int rr = lr + 8 * ri;
            float s = 0.f;
            #pragma unroll
            for (int dd = 0; dd < 16; dd++) {
                int d = d0 + dd;
                float qv = __bfloat162float(*(__nv_bfloat16*)(smraw + AQH + rr * ARS + d * 2))
                         + __bfloat162float(*(__nv_bfloat16*)(smraw + AQL + rr * ARS + d * 2));
                float kv = __bfloat162float(*(__nv_bfloat16*)(smraw + AHKH + rr * ARS + d * 2))
                         + __bfloat162float(*(__nv_bfloat16*)(smraw + AHKL + rr * ARS + d * 2));
                s = fmaf(qv, kv, s);
            }
            s += __shfl_xor_sync(0xffffffffu, s, 1);
            s += __shfl_xor_sync(0xffffffffu, s, 2);
            qhk[ri] = s;
        }
    }

    const float sigA = 1.f / (1.f + __expf(-alpha[h]));
    float rmax[2] = {NEGINF, NEGINF}, lsum[2] = {0.f, 0.f}, accm[2] = {0.f, 0.f};
    float acco[8][4];
    #pragma unroll
    for (int nb = 0; nb < 8; nb++)
        #pragma unroll
        for (int e = 0; e < 4; e++) acco[nb][e] = 0.f;

    for (int kt = 0; kt <= ktend; kt++) {
        if (kt < ktend) cp_wait<1>(); else cp_wait<0>();
        __syncthreads();
        const uint32_t kvb = sb + AKV + (kt & 1) * KVS;

        float S1[8][4], S2[8][4], S3[8][4];
        #pragma unroll
        for (int nb = 0; nb < 8; nb++)
            #pragma unroll
            for (int e = 0; e < 4; e++) { S1[nb][e] = 0.f; S2[nb][e] = 0.f; S3[nb][e] = 0.f; }

        #pragma unroll
        for (int ks = 0; ks < 4; ks++) {
            uint32_t aQh[4], aQl[4], aKh2[4], aKl2[4], aVh2[4], aVl2[4];
            uint32_t abase = sb + (w * 16 + (lane & 15)) * ARS + ((lane >> 4) + 2 * ks) * 16;
            ldsm4(aQh,  abase + AQH);
            ldsm4(aQl,  abase + AQL);
            ldsm4(aKh2, abase + AHKH);
            ldsm4(aKl2, abase + AHKL);
            ldsm4(aVh2, abase + AHVH);
            ldsm4(aVl2, abase + AHVL);
            #pragma unroll
            for (int np = 0; np < 4; np++) {
                uint32_t bKh[4], bKl[4], bVh[4], bVl[4];
                uint32_t bbase = kvb + (np * 16 + (lane & 15)) * ARS + ((lane >> 4) + 2 * ks) * 16;
                ldsm4(bKh, bbase + KOFF_KH);
                ldsm4(bKl, bbase + KOFF_KL);
                ldsm4(bVh, bbase + KOFF_VH);
                ldsm4(bVl, bbase + KOFF_VL);
                #pragma unroll
                for (int hf = 0; hf < 2; hf++) {
                    int nb = np * 2 + hf;
                    mma_bf16(S1[nb], aQh,  bKh[hf], bKh[hf + 2]);
                    mma_bf16(S1[nb], aQh,  bKl[hf], bKl[hf + 2]);
                    mma_bf16(S1[nb], aQl,  bKh[hf], bKh[hf + 2]);
                    mma_bf16(S2[nb], aKh2, bKh[hf], bKh[hf + 2]);
                    mma_bf16(S2[nb], aKh2, bKl[hf], bKl[hf + 2]);
                    mma_bf16(S2[nb], aKl2, bKh[hf], bKh[hf + 2]);
                    mma_bf16(S3[nb], aVh2, bVh[hf], bVh[hf + 2]);
                    mma_bf16(S3[nb], aVh2, bVl[hf], bVl[hf + 2]);
                    mma_bf16(S3[nb], aVl2, bVh[hf], bVh[hf + 2]);
                }
            }
        }

        // ---- softmax with silu-modulated scores ----
        const bool needmask = (kt >= 2 * qt);
        float tmax[2] = {NEGINF, NEGINF};
        #pragma unroll
        for (int nb = 0; nb < 8; nb++)
            #pragma unroll
            for (int e = 0; e < 4; e++) {
                int ri = e >> 1;
                float z = S2[nb][e] * qhk[ri] * SCALE;
                float sil = z / (1.f + __expf(-z));
                float s = S1[nb][e] * SCALE - sil;
                if (needmask) {
                    int colg = kt * 64 + nb * 8 + (lane & 3) * 2 + (e & 1);
                    int rowg = qt * 128 + lr + 8 * ri;
                    if (colg > rowg) s = NEGINF;
                }
                S1[nb][e] = s;
                tmax[ri] = fmaxf(tmax[ri], s);
            }
        float scv[2];
        #pragma unroll
        for (int ri = 0; ri < 2; ri++) {
            float t = tmax[ri];
            t = fmaxf(t, __shfl_xor_sync(0xffffffffu, t, 1));
            t = fmaxf(t, __shfl_xor_sync(0xffffffffu, t, 2));
            float nm = fmaxf(rmax[ri], t);
            float sc = __expf(rmax[ri] - nm);
            rmax[ri] = nm;
            lsum[ri] *= sc; accm[ri] *= sc;
            scv[ri] = sc;
        }
        #pragma unroll
        for (int nb = 0; nb < 8; nb++) {
            acco[nb][0] *= scv[0]; acco[nb][1] *= scv[0];
            acco[nb][2] *= scv[1]; acco[nb][3] *= scv[1];
        }
        #pragma unroll
        for (int nb = 0; nb < 8; nb++)
            #pragma unroll
            for (int e = 0; e < 4; e++) {
                int ri = e >> 1;
                float p = __expf(S1[nb][e] - rmax[ri]);
                S1[nb][e] = p;
                lsum[ri] += p;
                accm[ri] = fmaf(p, S3[nb][e], accm[ri]);
            }

        // ---- acco += P @ V (P from registers, V^T via ldmatrix.trans) ----
        #pragma unroll
        for (int ks = 0; ks < 4; ks++) {
            uint32_t Ph[4], Pl[4];
            pack_hilo(S1[2 * ks][0],     S1[2 * ks][1],     Ph[0], Pl[0]);
            pack_hilo(S1[2 * ks][2],     S1[2 * ks][3],     Ph[1], Pl[1]);
            pack_hilo(S1[2 * ks + 1][0], S1[2 * ks + 1][1], Ph[2], Pl[2]);
            pack_hilo(S1[2 * ks + 1][2], S1[2 * ks + 1][3], Ph[3], Pl[3]);
            #pragma unroll
            for (int np = 0; np < 4; np++) {
                uint32_t tVh[4], tVl[4];
                uint32_t tb2 = kvb + (ks * 16 + (lane & 7) + ((lane >> 4) & 1) * 8) * ARS
                             + (np * 2 + ((lane >> 3) & 1)) * 16;
                ldsm4t(tVh, tb2 + KOFF_VH);
                ldsm4t(tVl, tb2 + KOFF_VL);
                #pragma unroll
                for (int hf = 0; hf < 2; hf++) {
                    int nb = np * 2 + hf;
                    mma_bf16(acco[nb], Ph, tVh[hf], tVh[hf + 2]);
                    mma_bf16(acco[nb], Ph, tVl[hf], tVl[hf + 2]);
                    mma_bf16(acco[nb], Pl, tVh[hf], tVh[hf + 2]);
                }
            }
        }

        __syncthreads();                  // all reads of buf (kt&1) done
        if (kt + 2 <= ktend) kv_load(kt + 2, kt & 1);
    }

    // ---- final reduction + epilogue (bf16 hi/lo for output GEMM) ----
    float inv[2], mo[2];
    #pragma unroll
    for (int ri = 0; ri < 2; ri++) {
        float lv = lsum[ri], mv = accm[ri];
        lv += __shfl_xor_sync(0xffffffffu, lv, 1);
        lv += __shfl_xor_sync(0xffffffffu, lv, 2);
        mv += __shfl_xor_sync(0xffffffffu, mv, 1);
        mv += __shfl_xor_sync(0xffffffffu, mv, 2);
        inv[ri] = 1.f / lv;
        mo[ri] = mv * inv[ri] * sigA;
    }
    #pragma unroll
    for (int nb = 0; nb < 8; nb++) {
        int d0 = nb * 8 + (lane & 3) * 2;
        #pragma unroll
        for (int ri = 0; ri < 2; ri++) {
            int rl = lr + 8 * ri;
            __nv_bfloat162 hvh = *(__nv_bfloat162*)(smraw + AHVH + rl * ARS + d0 * 2);
            __nv_bfloat162 hvl = *(__nv_bfloat162*)(smraw + AHVL + rl * ARS + d0 * 2);
            float hv0 = __bfloat162float(hvh.x) + __bfloat162float(hvl.x);
            float hv1 = __bfloat162float(hvh.y) + __bfloat162float(hvl.y);
            float ox = acco[nb][2 * ri + 0] * inv[ri] - mo[ri] * hv0;
            float oy = acco[nb][2 * ri + 1] * inv[ri] - mo[ri] * hv1;
            uint32_t hp, lp;
            pack_hilo(ox, oy, hp, lp);
            size_t go = ((size_t)(b * NSEQ + qt * 128 + rl)) * DMOD + h * DH + d0;
            *(uint32_t*)(Oh + go) = hp;
            *(uint32_t*)(Ol + go) = lp;
        }
    }
}

// ---------------- launcher --------------------------------------------------
extern "C" void kernel_launch(void* const* d_in, const int* in_sizes, int n_in,
                              void* d_out, int out_size)
{
    const float* x     = (const float*)d_in[0];
    const float* w_qkv = (const float*)d_in[1];
    const float* w_hkv = (const float*)d_in[2];
    const float* w_out = (const float*)d_in[3];
    const float* b_out = (const float*)d_in[4];
    const float* alpha = (const float*)d_in[5];
    float* out = (float*)d_out;

    float *xwq, *xwh;
    __nv_bfloat16 *Qh,*Ql,*Kh,*Kl,*Vh,*Vl,*HKh,*HKl,*HVh,*HVl;
    __nv_bfloat16 *Axh, *Axl, *Ath, *Atl, *Bqh, *Bql, *Bhh, *Bhl, *Boh, *Bol;
    cudaGetSymbolAddress((void**)&xwq,  g_xw_qkv);
    cudaGetSymbolAddress((void**)&xwh,  g_xw_hkv);
    cudaGetSymbolAddress((void**)&Qh,   g_Qh);
    cudaGetSymbolAddress((void**)&Ql,   g_Ql);
    cudaGetSymbolAddress((void**)&Kh,   g_Kh);
    cudaGetSymbolAddress((void**)&Kl,   g_Kl);
    cudaGetSymbolAddress((void**)&Vh,   g_Vh);
    cudaGetSymbolAddress((void**)&Vl,   g_Vl);
    cudaGetSymbolAddress((void**)&HKh,  g_HKh);
    cudaGetSymbolAddress((void**)&HKl,  g_HKl);
    cudaGetSymbolAddress((void**)&HVh,  g_HVh);
    cudaGetSymbolAddress((void**)&HVl,  g_HVl);
    cudaGetSymbolAddress((void**)&Axh,  g_Axh);
    cudaGetSymbolAddress((void**)&Axl,  g_Axl);
    cudaGetSymbolAddress((void**)&Ath,  g_Ath);
    cudaGetSymbolAddress((void**)&Atl,  g_Atl);
    cudaGetSymbolAddress((void**)&Bqh,  g_Bqh);
    cudaGetSymbolAddress((void**)&Bql,  g_Bql);
    cudaGetSymbolAddress((void**)&Bhh,  g_Bhh);
    cudaGetSymbolAddress((void**)&Bhl,  g_Bhl);
    cudaGetSymbolAddress((void**)&Boh,  g_Boh);
    cudaGetSymbolAddress((void**)&Bol,  g_Bol);

    cudaFuncSetAttribute(gemm_tc, cudaFuncAttributeMaxDynamicSharedMemorySize, GSMEM);
    cudaFuncSetAttribute(attn_mma, cudaFuncAttributeMaxDynamicSharedMemorySize, ATT_SMEM);

    // 0) pack GEMM operands
    packA_k<<<(MROWS * DMOD / 4 + 255) / 256, 256>>>(x, Axh, Axl, MROWS * DMOD / 4);
    packB_k<<<dim3(3 * DMOD / 32, DMOD / 32), 256>>>(w_qkv, Bqh, Bql, DMOD, 3 * DMOD);
    packB_k<<<dim3(2 * DMOD / 32, DMOD / 32), 256>>>(w_hkv, Bhh, Bhl, DMOD, 2 * DMOD);
    packB_k<<<dim3(DMOD / 32, DMOD / 32), 256>>>(w_out, Boh, Bol, DMOD, DMOD);

    // 1) fused projections (qkv | hkv) in one launch
    gemm_tc<<<dim3(3 * DMOD / 128 + 2 * DMOD / 128, MROWS / 128), 128, GSMEM>>>(
        Axh, Axl, Bqh, Bql, Bhh, Bhl, nullptr, xwq, xwh,
        3 * DMOD, 2 * DMOD, DMOD, 3 * DMOD / 128, 0);

    // 2) head scatter + RoPE -> bf16 hi/lo
    {
        int total = BB * HN * NSEQ * (DH / 2);
        scatter_rope_k<<<(total + 255) / 256, 256>>>(
            xwq, xwh, Qh, Ql, Kh, Kl, Vh, Vl, HKh, HKl, HVh, HVl);
    }

    // 3) tensor-core flash attention (writes bf16 hi/lo A operand directly)
    attn_mma<<<dim3(BB * HN, NSEQ / 128), 256, ATT_SMEM>>>(
        Qh, Ql, Kh, Kl, Vh, Vl, HKh, HKl, HVh, HVl, alpha, Ath, Atl);

    // 4) output projection + bias
    gemm_tc<<<dim3(DMOD / 128, MROWS / 128), 128, GSMEM>>>(
        Ath, Atl, Boh, Bol, Boh, Bol, b_out, out, out,
        DMOD, DMOD, DMOD, DMOD / 128, 1);
}

// round 15
// speedup vs baseline: 2.8542x; 1.2145x over previous
#include <cuda_runtime.h>
#include <cuda_bf16.h>
#include <math.h>
#include <stdint.h>

// Problem constants
#define BB    2
#define NSEQ  2048
#define DMOD  1024
#define HN    16
#define DH    64
#define MROWS (BB*NSEQ)          // 4096
#define SCALE 0.125f             // Dh^-0.5

// ---------------- scratch (device globals: allocation-free) ----------------
// bf16 hi/lo head tensors [bh][n][64]
#define HT ((size_t)BB*HN*NSEQ*DH)
__device__ __align__(256) __nv_bfloat16 g_Qh[HT],  g_Ql[HT];
__device__ __align__(256) __nv_bfloat16 g_Kh[HT],  g_Kl[HT];
__device__ __align__(256) __nv_bfloat16 g_Vh[HT],  g_Vl[HT];
__device__ __align__(256) __nv_bfloat16 g_HKh[HT], g_HKl[HT];
__device__ __align__(256) __nv_bfloat16 g_HVh[HT], g_HVl[HT];

// packed bf16 GEMM operands
__device__ __align__(256) __nv_bfloat16 g_Axh[(size_t)MROWS * DMOD];
__device__ __align__(256) __nv_bfloat16 g_Axl[(size_t)MROWS * DMOD];
__device__ __align__(256) __nv_bfloat16 g_Ath[(size_t)MROWS * DMOD];   // attn out hi
__device__ __align__(256) __nv_bfloat16 g_Atl[(size_t)MROWS * DMOD];   // attn out lo
__device__ __align__(256) __nv_bfloat16 g_Bqh[(size_t)3 * DMOD * DMOD];
__device__ __align__(256) __nv_bfloat16 g_Bql[(size_t)3 * DMOD * DMOD];
__device__ __align__(256) __nv_bfloat16 g_Bhh[(size_t)2 * DMOD * DMOD];
__device__ __align__(256) __nv_bfloat16 g_Bhl[(size_t)2 * DMOD * DMOD];
__device__ __align__(256) __nv_bfloat16 g_Boh[(size_t)DMOD * DMOD];
__device__ __align__(256) __nv_bfloat16 g_Bol[(size_t)DMOD * DMOD];

// ======================= PTX helpers (compute_103-safe) ====================
__device__ __forceinline__ uint32_t smem_u32(const void* p) {
    uint32_t a;
    asm("{ .reg .u64 t; cvta.to.shared.u64 t, %1; cvt.u32.u64 %0, t; }" : "=r"(a) : "l"(p));
    return a;
}
__device__ __forceinline__ void cpasync16(uint32_t dst, const void* src) {
    asm volatile("cp.async.cg.shared.global [%0], [%1], 16;" :: "r"(dst), "l"(src));
}
__device__ __forceinline__ void cp_commit() {
    asm volatile("cp.async.commit_group;");
}
template<int N>
__device__ __forceinline__ void cp_wait() {
    asm volatile("cp.async.wait_group %0;" :: "n"(N));
}
__device__ __forceinline__ void ldsm4(uint32_t* r, uint32_t addr) {
    asm volatile("ldmatrix.sync.aligned.m8n8.x4.shared.b16 {%0,%1,%2,%3}, [%4];"
        : "=r"(r[0]), "=r"(r[1]), "=r"(r[2]), "=r"(r[3]) : "r"(addr));
}
__device__ __forceinline__ void ldsm4t(uint32_t* r, uint32_t addr) {
    asm volatile("ldmatrix.sync.aligned.m8n8.x4.trans.shared.b16 {%0,%1,%2,%3}, [%4];"
        : "=r"(r[0]), "=r"(r[1]), "=r"(r[2]), "=r"(r[3]) : "r"(addr));
}
__device__ __forceinline__ void mma_bf16(float* d, const uint32_t* a,
                                         uint32_t b0, uint32_t b1) {
    asm volatile("mma.sync.aligned.m16n8k16.row.col.f32.bf16.bf16.f32 "
        "{%0,%1,%2,%3}, {%4,%5,%6,%7}, {%8,%9}, {%0,%1,%2,%3};"
        : "+f"(d[0]), "+f"(d[1]), "+f"(d[2]), "+f"(d[3])
        : "r"(a[0]), "r"(a[1]), "r"(a[2]), "r"(a[3]), "r"(b0), "r"(b1));
}
__device__ __forceinline__ void pack_hilo(float a, float b, uint32_t& hr, uint32_t& lr2) {
    __nv_bfloat16 ah = __float2bfloat16(a), bh = __float2bfloat16(b);
    float ar = a - __bfloat162float(ah), br = b - __bfloat162float(bh);
    __nv_bfloat162 hp; hp.x = ah; hp.y = bh;
    __nv_bfloat162 lp; lp.x = __float2bfloat16(ar); lp.y = __float2bfloat16(br);
    hr = *(uint32_t*)&hp;
    lr2 = *(uint32_t*)&lp;
}

// ======================= pack kernels ======================================
__global__ __launch_bounds__(256) void packA_k(
    const float* __restrict__ A, __nv_bfloat16* __restrict__ hi,
    __nv_bfloat16* __restrict__ lo, int n4)
{
    int idx = blockIdx.x * blockDim.x + threadIdx.x;
    if (idx >= n4) return;
    float4 v = ((const float4*)A)[idx];
    __nv_bfloat16 h[4], l[4];
    float vv[4] = {v.x, v.y, v.z, v.w};
    #pragma unroll
    for (int i = 0; i < 4; i++) {
        h[i] = __float2bfloat16(vv[i]);
        l[i] = __float2bfloat16(vv[i] - __bfloat162float(h[i]));
    }
    ((uint2*)hi)[idx] = *(uint2*)h;
    ((uint2*)lo)[idx] = *(uint2*)l;
}

// Dual-weight packB: blocks x < N1/32 pack W1, rest pack W2.
__global__ __launch_bounds__(256) void packB2_k(
    const float* __restrict__ W1, __nv_bfloat16* __restrict__ h1, __nv_bfloat16* __restrict__ l1, int N1,
    const float* __restrict__ W2, __nv_bfloat16* __restrict__ h2, __nv_bfloat16* __restrict__ l2, int N2,
    int K)
{
    __shared__ float s[32][33];
    const float* W; __nv_bfloat16 *hi, *lo; int N, n0;
    int nx1 = N1 / 32;
    if ((int)blockIdx.x < nx1) { W = W1; hi = h1; lo = l1; N = N1; n0 = blockIdx.x * 32; }
    else { W = W2; hi = h2; lo = l2; N = N2; n0 = (blockIdx.x - nx1) * 32; }
    int k0 = blockIdx.y * 32;
    int tx = threadIdx.x & 31, ty = threadIdx.x >> 5;
    #pragma unroll
    for (int i = 0; i < 4; i++) {
        int k = ty + i * 8;
        s[k][tx] = W[(size_t)(k0 + k) * N + n0 + tx];
    }
    __syncthreads();
    #pragma unroll
    for (int i = 0; i < 4; i++) {
        int nl = ty + i * 8;
        float v = s[tx][nl];
        __nv_bfloat16 h = __float2bfloat16(v);
        __nv_bfloat16 l = __float2bfloat16(v - __bfloat162float(h));
        size_t o = (size_t)(n0 + nl) * K + k0 + tx;
        hi[o] = h;
        lo[o] = l;
    }
}

// ======================= mma.sync bf16 GEMM ================================
// CTA: 128x128 tile, BK=32, 128 threads = 4 warps (2x2), warp tile 64x64.
// Dual-output: blocks with bx < nx1 use B1, others B2.
// mode 0: write fp32 C (+bias).  mode 1: fused RoPE + head-scatter epilogue
// writing bf16 hi/lo head tensors directly (C1 = qkv, C2 = hkv).
#define GLDB   80
#define MATB   (128 * GLDB)            // 10240
#define STAGEB (4 * MATB)              // 40960
#define GSMEM  (2 * STAGEB)            // 81920

__global__ __launch_bounds__(128) void gemm_tc(
    const __nv_bfloat16* __restrict__ Ahi, const __nv_bfloat16* __restrict__ Alo,
    const __nv_bfloat16* __restrict__ B1h, const __nv_bfloat16* __restrict__ B1l,
    const __nv_bfloat16* __restrict__ B2h, const __nv_bfloat16* __restrict__ B2l,
    const float* __restrict__ bias,
    float* __restrict__ C1, float* __restrict__ C2,
    int N1, int N2, int K, int nx1, int hasBias, int mode)
{
    extern __shared__ char smraw[];
    const uint32_t sb = smem_u32(smraw);
    const int tid = threadIdx.x;
    const int lane = tid & 31, wid = tid >> 5;
    const int wm = wid >> 1;          // 0..1
    const int wn = wid & 1;           // 0..1

    const int bm = blockIdx.y * 128;
    const bool isC1 = ((int)blockIdx.x < nx1);
    const __nv_bfloat16 *Bh_, *Bl_;
    float* C;
    int N, bn;
    if (isC1) {
        Bh_ = B1h; Bl_ = B1l; C = C1; N = N1; bn = blockIdx.x * 128;
    } else {
        Bh_ = B2h; Bl_ = B2l; C = C2; N = N2; bn = (blockIdx.x - nx1) * 128;
    }

    const __nv_bfloat16* srcs[4] = {
        Ahi + (size_t)bm * K, Alo + (size_t)bm * K,
        Bh_ + (size_t)bn * K, Bl_ + (size_t)bn * K };

    auto load_stage = [&](int st, int kc) {
        #pragma unroll
        for (int i = 0; i < 16; i++) {
            int idx = tid + i * 128;
            int mat = idx >> 9;
            int rem = idx & 511;
            int r = rem >> 2, ch = rem & 3;
            cpasync16(sb + st * STAGEB + mat * MATB + r * GLDB + ch * 16,
                      srcs[mat] + (size_t)r * K + kc * 32 + ch * 8);
        }
        cp_commit();
    };

    float acc[4][8][4];
    #pragma unroll
    for (int a = 0; a < 4; a++)
        #pragma unroll
        for (int b = 0; b < 8; b++)
            #pragma unroll
            for (int c = 0; c < 4; c++) acc[a][b][c] = 0.f;

    const int KC = K >> 5;
    load_stage(0, 0);

    const int arow = lane & 15;
    const int ahalf = (lane >> 4) << 3;

    for (int kc = 0; kc < KC; kc++) {
        int cur = kc & 1;
        if (kc + 1 < KC) load_stage(1 - cur, kc + 1);
        if (kc + 1 < KC) cp_wait<1>(); else cp_wait<0>();
        __syncthreads();

        #pragma unroll
        for (int kk = 0; kk < 32; kk += 16) {
            uint32_t ah[4][4], al[4][4];
            int acol = kk + ahalf;
            uint32_t stb = sb + cur * STAGEB;
            #pragma unroll
            for (int mb = 0; mb < 4; mb++) {
                uint32_t ad = stb + (wm * 64 + mb * 16 + arow) * GLDB + acol * 2;
                ldsm4(ah[mb], ad);
                ldsm4(al[mb], ad + MATB);
            }
            #pragma unroll
            for (int np = 0; np < 4; np++) {
                uint32_t bh[4], bl[4];
                uint32_t bd = stb + 2 * MATB + (wn * 64 + np * 16 + arow) * GLDB + acol * 2;
                ldsm4(bh, bd);
                ldsm4(bl, bd + MATB);
                #pragma unroll
                for (int mb = 0; mb < 4; mb++)
                    #pragma unroll
                    for (int hf = 0; hf < 2; hf++) {
                        int nb = np * 2 + hf;
                        mma_bf16(acc[mb][nb], ah[mb], bh[hf], bh[hf + 2]);
                        mma_bf16(acc[mb][nb], ah[mb], bl[hf], bl[hf + 2]);
                        mma_bf16(acc[mb][nb], al[mb], bh[hf], bh[hf + 2]);
                    }
            }
        }
        __syncthreads();
    }

    if (mode == 0) {
        #pragma unroll
        for (int mb = 0; mb < 4; mb++) {
            int r0 = bm + wm * 64 + mb * 16 + (lane >> 2);
            #pragma unroll
            for (int nb = 0; nb < 8; nb++) {
                int c0 = bn + wn * 64 + nb * 8 + (lane & 3) * 2;
                float bx = 0.f, by = 0.f;
                if (hasBias) { bx = bias[c0]; by = bias[c0 + 1]; }
                float2 v0 = { acc[mb][nb][0] + bx, acc[mb][nb][1] + by };
                float2 v1 = { acc[mb][nb][2] + bx, acc[mb][nb][3] + by };
                *(float2*)(C + (size_t)r0 * N + c0) = v0;
                *(float2*)(C + (size_t)(r0 + 8) * N + c0) = v1;
            }
        }
    } else {
        // fused RoPE + head-scatter epilogue -> bf16 hi/lo head tensors
        #pragma unroll
        for (int nb = 0; nb < 8; nb++) {
            int c0 = bn + wn * 64 + nb * 8 + (lane & 3) * 2;
            int kind = c0 >> 10;                 // C1: 0=q 1=k 2=v; C2: 0=hk 1=hv
            int hh = (c0 & 1023) >> 6;
            int d = c0 & 63;                     // even
            bool doRope = isC1 && (kind < 2);
            double freq = doRope ? pow(10000.0, -(double)d / 64.0) : 0.0;
            __nv_bfloat16 *H, *L;
            if (isC1) {
                H = (kind == 0) ? g_Qh : (kind == 1) ? g_Kh : g_Vh;
                L = (kind == 0) ? g_Ql : (kind == 1) ? g_Kl : g_Vl;
            } else {
                H = (kind == 0) ? g_HKh : g_HVh;
                L = (kind == 0) ? g_HKl : g_HVl;
            }
            #pragma unroll
            for (int mb = 0; mb < 4; mb++) {
                #pragma unroll
                for (int ri = 0; ri < 2; ri++) {
                    int r = bm + wm * 64 + mb * 16 + (lane >> 2) + ri * 8;
                    int n = r & (NSEQ - 1), bb = r >> 11;
                    float a0 = acc[mb][nb][ri * 2 + 0];
                    float a1 = acc[mb][nb][ri * 2 + 1];
                    if (doRope) {
                        float ang = (float)((double)n * freq);
                        float sn, cs;
                        sincosf(ang, &sn, &cs);
                        float t0 = a0 * cs - a1 * sn;
                        float t1 = a1 * cs + a0 * sn;
                        a0 = t0; a1 = t1;
                    }
                    uint32_t hp, lp;
                    pack_hilo(a0, a1, hp, lp);
                    size_t o = (((size_t)(bb * HN + hh) * NSEQ) + n) * DH + d;
                    *(uint32_t*)(H + o) = hp;
                    *(uint32_t*)(L + o) = lp;
                }
            }
        }
    }
}

// ---------------- tensor-core flash attention ------------------------------
// CTA = 128 q-rows of one (b,h); 8 warps x 16 rows; k-tiles of 64,
// K/V tiles double-buffered (2-stage cp.async ring).
#define ARS   144
#define AQH   0
#define AQL   (1 * 128 * ARS)
#define AHKH  (2 * 128 * ARS)
#define AHKL  (3 * 128 * ARS)
#define AHVH  (4 * 128 * ARS)
#define AHVL  (5 * 128 * ARS)
#define AKV   (6 * 128 * ARS)          // 110592: KV ring base
#define KVS   (4 * 64 * ARS)           // 36864 per stage
#define KOFF_KH 0
#define KOFF_KL (64 * ARS)
#define KOFF_VH (2 * 64 * ARS)
#define KOFF_VL (3 * 64 * ARS)
#define ATT_SMEM (AKV + 2 * KVS)       // 184320

__global__ __launch_bounds__(256) void attn_mma(
    const __nv_bfloat16* __restrict__ Qh, const __nv_bfloat16* __restrict__ Ql,
    const __nv_bfloat16* __restrict__ Kh, const __nv_bfloat16* __restrict__ Kl,
    const __nv_bfloat16* __restrict__ Vh, const __nv_bfloat16* __restrict__ Vl,
    const __nv_bfloat16* __restrict__ HKh, const __nv_bfloat16* __restrict__ HKl,
    const __nv_bfloat16* __restrict__ HVh, const __nv_bfloat16* __restrict__ HVl,
    const float* __restrict__ alpha,
    __nv_bfloat16* __restrict__ Oh, __nv_bfloat16* __restrict__ Ol)
{
    extern __shared__ char smraw[];
    const uint32_t sb = smem_u32(smraw);
    const int tid = threadIdx.x, lane = tid & 31, w = tid >> 5;
    const int bh = blockIdx.x;
    const int qt = (NSEQ / 128 - 1) - blockIdx.y;   // biggest tiles first
    const int h = bh & (HN - 1), b = bh >> 4;
    const size_t gbase = (size_t)bh * NSEQ * DH;
    const float NEGINF = __int_as_float(0xff800000);
    const int ktend = 2 * qt + 1;

    auto kv_load = [&](int kt, int stage) {
        const size_t koff = gbase + (size_t)kt * 64 * DH;
        const __nv_bfloat16* kp[4] = { Kh + koff, Kl + koff, Vh + koff, Vl + koff };
        #pragma unroll
        for (int i = 0; i < 8; i++) {
            int idx = tid + i * 256;
            int arr = idx >> 9, rem = idx & 511;
            int row = rem >> 3, ch = rem & 7;
            cpasync16(sb + AKV + stage * KVS + arr * (64 * ARS) + row * ARS + ch * 16,
                      kp[arr] + row * DH + ch * 8);
        }
        cp_commit();
    };

    // ---- prologue: Q/HK/HV tiles + first two KV tiles ----
    {
        const size_t qoff = gbase + (size_t)qt * 128 * DH;
        const __nv_bfloat16* ap[6] = { Qh + qoff, Ql + qoff, HKh + qoff,
                                       HKl + qoff, HVh + qoff, HVl + qoff };
        #pragma unroll
        for (int i = 0; i < 24; i++) {
            int idx = tid + i * 256;
            int arr = idx >> 10, rem = idx & 1023;
            int row = rem >> 3, ch = rem & 7;
            cpasync16(sb + arr * (128 * ARS) + row * ARS + ch * 16,
                      ap[arr] + row * DH + ch * 8);
        }
        cp_commit();
    }
    kv_load(0, 0);
    kv_load(1, 1);          // ktend >= 1 always
    cp_wait<2>();           // Q/HK/HV complete
    __syncthreads();

    // ---- qhk per row (2 rows/thread) ----
    const int lr = w * 16 + (lane >> 2);
    float qhk[2];
    {
        const int d0 = (lane & 3) * 16;
        #pragma unroll
        for (int ri = 0; ri < 2; ri++) {
            int rr = lr + 8 * ri;
            float s = 0.f;
            #pragma unroll
            for (int dd = 0; dd < 16; dd++) {
                int d = d0 + dd;
                float qv = __bfloat162float(*(__nv_bfloat16*)(smraw + AQH + rr * ARS + d * 2))
                         + __bfloat162float(*(__nv_bfloat16*)(smraw + AQL + rr * ARS + d * 2));
                float kv = __bfloat162float(*(__nv_bfloat16*)(smraw + AHKH + rr * ARS + d * 2))
                         + __bfloat162float(*(__nv_bfloat16*)(smraw + AHKL + rr * ARS + d * 2));
                s = fmaf(qv, kv, s);
            }
            s += __shfl_xor_sync(0xffffffffu, s, 1);
            s += __shfl_xor_sync(0xffffffffu, s, 2);
            qhk[ri] = s;
        }
    }

    const float sigA = 1.f / (1.f + __expf(-alpha[h]));
    float rmax[2] = {NEGINF, NEGINF}, lsum[2] = {0.f, 0.f}, accm[2] = {0.f, 0.f};
    float acco[8][4];
    #pragma unroll
    for (int nb = 0; nb < 8; nb++)
        #pragma unroll
        for (int e = 0; e < 4; e++) acco[nb][e] = 0.f;

    for (int kt = 0; kt <= ktend; kt++) {
        if (kt < ktend) cp_wait<1>(); else cp_wait<0>();
        __syncthreads();
        const uint32_t kvb = sb + AKV + (kt & 1) * KVS;

        float S1[8][4], S2[8][4], S3[8][4];
        #pragma unroll
        for (int nb = 0; nb < 8; nb++)
            #pragma unroll
            for (int e = 0; e < 4; e++) { S1[nb][e] = 0.f; S2[nb][e] = 0.f; S3[nb][e] = 0.f; }

        #pragma unroll
        for (int ks = 0; ks < 4; ks++) {
            uint32_t aQh[4], aQl[4], aKh2[4], aKl2[4], aVh2[4], aVl2[4];
            uint32_t abase = sb + (w * 16 + (lane & 15)) * ARS + ((lane >> 4) + 2 * ks) * 16;
            ldsm4(aQh,  abase + AQH);
            ldsm4(aQl,  abase + AQL);
            ldsm4(aKh2, abase + AHKH);
            ldsm4(aKl2, abase + AHKL);
            ldsm4(aVh2, abase + AHVH);
            ldsm4(aVl2, abase + AHVL);
            #pragma unroll
            for (int np = 0; np < 4; np++) {
                uint32_t bKh[4], bKl[4], bVh[4], bVl[4];
                uint32_t bbase = kvb + (np * 16 + (lane & 15)) * ARS + ((lane >> 4) + 2 * ks) * 16;
                ldsm4(bKh, bbase + KOFF_KH);
                ldsm4(bKl, bbase + KOFF_KL);
                ldsm4(bVh, bbase + KOFF_VH);
                ldsm4(bVl, bbase + KOFF_VL);
                #pragma unroll
                for (int hf = 0; hf < 2; hf++) {
                    int nb = np * 2 + hf;
                    mma_bf16(S1[nb], aQh,  bKh[hf], bKh[hf + 2]);
                    mma_bf16(S1[nb], aQh,  bKl[hf], bKl[hf + 2]);
                    mma_bf16(S1[nb], aQl,  bKh[hf], bKh[hf + 2]);
                    mma_bf16(S2[nb], aKh2, bKh[hf], bKh[hf + 2]);
                    mma_bf16(S2[nb], aKh2, bKl[hf], bKl[hf + 2]);
                    mma_bf16(S2[nb], aKl2, bKh[hf], bKh[hf + 2]);
                    mma_bf16(S3[nb], aVh2, bVh[hf], bVh[hf + 2]);
                    mma_bf16(S3[nb], aVh2, bVl[hf], bVl[hf + 2]);
                    mma_bf16(S3[nb], aVl2, bVh[hf], bVh[hf + 2]);
                }
            }
        }

        // ---- softmax with silu-modulated scores ----
        const bool needmask = (kt >= 2 * qt);
        float tmax[2] = {NEGINF, NEGINF};
        #pragma unroll
        for (int nb = 0; nb < 8; nb++)
            #pragma unroll
            for (int e = 0; e < 4; e++) {
                int ri = e >> 1;
                float z = S2[nb][e] * qhk[ri] * SCALE;
                float sil = z / (1.f + __expf(-z));
                float s = S1[nb][e] * SCALE - sil;
                if (needmask) {
                    int colg = kt * 64 + nb * 8 + (lane & 3) * 2 + (e & 1);
                    int rowg = qt * 128 + lr + 8 * ri;
                    if (colg > rowg) s = NEGINF;
                }
                S1[nb][e] = s;
                tmax[ri] = fmaxf(tmax[ri], s);
            }
        float scv[2];
        #pragma unroll
        for (int ri = 0; ri < 2; ri++) {
            float t = tmax[ri];
            t = fmaxf(t, __shfl_xor_sync(0xffffffffu, t, 1));
            t = fmaxf(t, __shfl_xor_sync(0xffffffffu, t, 2));
            float nm = fmaxf(rmax[ri], t);
            float sc = __expf(rmax[ri] - nm);
            rmax[ri] = nm;
            lsum[ri] *= sc; accm[ri] *= sc;
            scv[ri] = sc;
        }
        #pragma unroll
        for (int nb = 0; nb < 8; nb++) {
            acco[nb][0] *= scv[0]; acco[nb][1] *= scv[0];
            acco[nb][2] *= scv[1]; acco[nb][3] *= scv[1];
        }
        #pragma unroll
        for (int nb = 0; nb < 8; nb++)
            #pragma unroll
            for (int e = 0; e < 4; e++) {
                int ri = e >> 1;
                float p = __expf(S1[nb][e] - rmax[ri]);
                S1[nb][e] = p;
                lsum[ri] += p;
                accm[ri] = fmaf(p, S3[nb][e], accm[ri]);
            }

        // ---- acco += P @ V (P from registers, V^T via ldmatrix.trans) ----
        #pragma unroll
        for (int ks = 0; ks < 4; ks++) {
            uint32_t Ph[4], Pl[4];
            pack_hilo(S1[2 * ks][0],     S1[2 * ks][1],     Ph[0], Pl[0]);
            pack_hilo(S1[2 * ks][2],     S1[2 * ks][3],     Ph[1], Pl[1]);
            pack_hilo(S1[2 * ks + 1][0], S1[2 * ks + 1][1], Ph[2], Pl[2]);
            pack_hilo(S1[2 * ks + 1][2], S1[2 * ks + 1][3], Ph[3], Pl[3]);
            #pragma unroll
            for (int np = 0; np < 4; np++) {
                uint32_t tVh[4], tVl[4];
                uint32_t tb2 = kvb + (ks * 16 + (lane & 7) + ((lane >> 4) & 1) * 8) * ARS
                             + (np * 2 + ((lane >> 3) & 1)) * 16;
                ldsm4t(tVh, tb2 + KOFF_VH);
                ldsm4t(tVl, tb2 + KOFF_VL);
                #pragma unroll
                for (int hf = 0; hf < 2; hf++) {
                    int nb = np * 2 + hf;
                    mma_bf16(acco[nb], Ph, tVh[hf], tVh[hf + 2]);
                    mma_bf16(acco[nb], Ph, tVl[hf], tVl[hf + 2]);
                    mma_bf16(acco[nb], Pl, tVh[hf], tVh[hf + 2]);
                }
            }
        }

        __syncthreads();                  // all reads of buf (kt&1) done
        if (kt + 2 <= ktend) kv_load(kt + 2, kt & 1);
    }

    // ---- final reduction + epilogue (bf16 hi/lo for output GEMM) ----
    float inv[2], mo[2];
    #pragma unroll
    for (int ri = 0; ri < 2; ri++) {
        float lv = lsum[ri], mv = accm[ri];
        lv += __shfl_xor_sync(0xffffffffu, lv, 1);
        lv += __shfl_xor_sync(0xffffffffu, lv, 2);
        mv += __shfl_xor_sync(0xffffffffu, mv, 1);
        mv += __shfl_xor_sync(0xffffffffu, mv, 2);
        inv[ri] = 1.f / lv;
        mo[ri] = mv * inv[ri] * sigA;
    }
    #pragma unroll
    for (int nb = 0; nb < 8; nb++) {
        int d0 = nb * 8 + (lane & 3) * 2;
        #pragma unroll
        for (int ri = 0; ri < 2; ri++) {
            int rl = lr + 8 * ri;
            __nv_bfloat162 hvh = *(__nv_bfloat162*)(smraw + AHVH + rl * ARS + d0 * 2);
            __nv_bfloat162 hvl = *(__nv_bfloat162*)(smraw + AHVL + rl * ARS + d0 * 2);
            float hv0 = __bfloat162float(hvh.x) + __bfloat162float(hvl.x);
            float hv1 = __bfloat162float(hvh.y) + __bfloat162float(hvl.y);
            float ox = acco[nb][2 * ri + 0] * inv[ri] - mo[ri] * hv0;
            float oy = acco[nb][2 * ri + 1] * inv[ri] - mo[ri] * hv1;
            uint32_t hp, lp;
            pack_hilo(ox, oy, hp, lp);
            size_t go = ((size_t)(b * NSEQ + qt * 128 + rl)) * DMOD + h * DH + d0;
            *(uint32_t*)(Oh + go) = hp;
            *(uint32_t*)(Ol + go) = lp;
        }
    }
}

// ---------------- launcher --------------------------------------------------
extern "C" void kernel_launch(void* const* d_in, const int* in_sizes, int n_in,
                              void* d_out, int out_size)
{
    const float* x     = (const float*)d_in[0];
    const float* w_qkv = (const float*)d_in[1];
    const float* w_hkv = (const float*)d_in[2];
    const float* w_out = (const float*)d_in[3];
    const float* b_out = (const float*)d_in[4];
    const float* alpha = (const float*)d_in[5];
    float* out = (float*)d_out;

    __nv_bfloat16 *Qh,*Ql,*Kh,*Kl,*Vh,*Vl,*HKh,*HKl,*HVh,*HVl;
    __nv_bfloat16 *Axh, *Axl, *Ath, *Atl, *Bqh, *Bql, *Bhh, *Bhl, *Boh, *Bol;
    cudaGetSymbolAddress((void**)&Qh,   g_Qh);
    cudaGetSymbolAddress((void**)&Ql,   g_Ql);
    cudaGetSymbolAddress((void**)&Kh,   g_Kh);
    cudaGetSymbolAddress((void**)&Kl,   g_Kl);
    cudaGetSymbolAddress((void**)&Vh,   g_Vh);
    cudaGetSymbolAddress((void**)&Vl,   g_Vl);
    cudaGetSymbolAddress((void**)&HKh,  g_HKh);
    cudaGetSymbolAddress((void**)&HKl,  g_HKl);
    cudaGetSymbolAddress((void**)&HVh,  g_HVh);
    cudaGetSymbolAddress((void**)&HVl,  g_HVl);
    cudaGetSymbolAddress((void**)&Axh,  g_Axh);
    cudaGetSymbolAddress((void**)&Axl,  g_Axl);
    cudaGetSymbolAddress((void**)&Ath,  g_Ath);
    cudaGetSymbolAddress((void**)&Atl,  g_Atl);
    cudaGetSymbolAddress((void**)&Bqh,  g_Bqh);
    cudaGetSymbolAddress((void**)&Bql,  g_Bql);
    cudaGetSymbolAddress((void**)&Bhh,  g_Bhh);
    cudaGetSymbolAddress((void**)&Bhl,  g_Bhl);
    cudaGetSymbolAddress((void**)&Boh,  g_Boh);
    cudaGetSymbolAddress((void**)&Bol,  g_Bol);

    cudaFuncSetAttribute(gemm_tc, cudaFuncAttributeMaxDynamicSharedMemorySize, GSMEM);
    cudaFuncSetAttribute(attn_mma, cudaFuncAttributeMaxDynamicSharedMemorySize, ATT_SMEM);

    // 1) pack A (x)
    packA_k<<<(MROWS * DMOD / 4 + 255) / 256, 256>>>(x, Axh, Axl, MROWS * DMOD / 4);

    // 2) pack both projection weights in one launch
    packB2_k<<<dim3(3 * DMOD / 32 + 2 * DMOD / 32, DMOD / 32), 256>>>(
        w_qkv, Bqh, Bql, 3 * DMOD, w_hkv, Bhh, Bhl, 2 * DMOD, DMOD);

    // 3) fused projections + RoPE + head-scatter (mode 1)
    gemm_tc<<<dim3(3 * DMOD / 128 + 2 * DMOD / 128, MROWS / 128), 128, GSMEM>>>(
        Axh, Axl, Bqh, Bql, Bhh, Bhl, nullptr, nullptr, nullptr,
        3 * DMOD, 2 * DMOD, DMOD, 3 * DMOD / 128, 0, 1);

    // 4) tensor-core flash attention  (launch #4 -> ncu capture slot)
    attn_mma<<<dim3(BB * HN, NSEQ / 128), 256, ATT_SMEM>>>(
        Qh, Ql, Kh, Kl, Vh, Vl, HKh, HKl, HVh, HVl, alpha, Ath, Atl);

    // 5) pack output weight
    packB2_k<<<dim3(DMOD / 32, DMOD / 32), 256>>>(
        w_out, Boh, Bol, DMOD, w_out, Boh, Bol, DMOD, DMOD);

    // 6) output projection + bias (mode 0)
    gemm_tc<<<dim3(DMOD / 128, MROWS / 128), 128, GSMEM>>>(
        Ath, Atl, Boh, Bol, Boh, Bol, b_out, out, out,
        DMOD, DMOD, DMOD, DMOD / 128, 1, 0);
}